// round 4
// baseline (speedup 1.0000x reference)
#include <cuda_runtime.h>
#include <math.h>
#include <stdint.h>

#define TT 1024
#define HH 2880
#define II 2880
#define EE 16
#define KTOP 4
#define NROWS (TT * KTOP)
#define ALPHA 1.702f
#define LIMIT 7.0f

// GEMM tiling: BM=128, BN=160, BK=32 floats (128B rows, SW128)
#define BM 128
#define BN 160
#define BK 32
#define NKT (HH / BK)            // 90
#define A_BYTES (BM * BK * 4)    // 16384
#define B_BYTES (BN * BK * 4)    // 20480
#define NSTB 3
#define SMEM_BYTES (2 * A_BYTES + NSTB * B_BYTES)   // 94208

// ---------------- scratch -----------------------------------------------
__device__ float g_gate[(size_t)NROWS * II];
__device__ float g_up[(size_t)NROWS * II];
__device__ float g_dn[(size_t)NROWS * HH];
__device__ int   g_offs[EE + 1];
__device__ int   g_pos[NROWS];
__device__ int   g_rowtok[NROWS];
__device__ float g_roww[NROWS];
__device__ int   g_tidx[NROWS];
__device__ float g_tw[NROWS];

// ---------------- helpers -----------------------------------------------
__device__ __forceinline__ unsigned f2tf(float x) {
    unsigned r;
    asm("cvt.rna.tf32.f32 %0, %1;" : "=r"(r) : "f"(x));
    return r;
}
__device__ __forceinline__ unsigned f2tf_u(unsigned x) {
    unsigned r;
    asm("cvt.rna.tf32.f32 %0, %1;" : "=r"(r) : "f"(__uint_as_float(x)));
    return r;
}
__device__ __forceinline__ uint32_t smem_u32(const void* p) {
    uint32_t a;
    asm("{ .reg .u64 t; cvta.to.shared.u64 t, %1; cvt.u32.u64 %0, t; }" : "=r"(a) : "l"(p));
    return a;
}
__device__ __forceinline__ uint32_t SWZ(uint32_t off) {
    return off ^ ((off >> 3) & 0x70u);
}
#define STS128(addr, a, b, c, d)                                            \
    asm volatile("st.shared.v4.b32 [%0], {%1,%2,%3,%4};" ::"r"(addr),        \
                 "r"(a), "r"(b), "r"(c), "r"(d) : "memory")
#define CP_ASYNC16(dst, src)                                                \
    asm volatile("cp.async.cg.shared.global [%0], [%1], 16;" ::"r"(dst), "l"(src) : "memory")
#define CP_COMMIT() asm volatile("cp.async.commit_group;" ::: "memory")
#define CP_WAIT1()  asm volatile("cp.async.wait_group 1;" ::: "memory")

__device__ __forceinline__ void ldsm4(unsigned* r, uint32_t addr) {
    asm volatile("ldmatrix.sync.aligned.m8n8.x4.shared.b16 {%0,%1,%2,%3}, [%4];"
                 : "=r"(r[0]), "=r"(r[1]), "=r"(r[2]), "=r"(r[3]) : "r"(addr));
}
__device__ __forceinline__ void ldsm2(unsigned* r, uint32_t addr) {
    asm volatile("ldmatrix.sync.aligned.m8n8.x2.shared.b16 {%0,%1}, [%2];"
                 : "=r"(r[0]), "=r"(r[1]) : "r"(addr));
}
__device__ __forceinline__ void mma8(float* d, const unsigned* a, const unsigned* b) {
    asm volatile(
        "mma.sync.aligned.m16n8k8.row.col.f32.tf32.tf32.f32 "
        "{%0,%1,%2,%3}, {%4,%5,%6,%7}, {%8,%9}, {%0,%1,%2,%3};"
        : "+f"(d[0]), "+f"(d[1]), "+f"(d[2]), "+f"(d[3])
        : "r"(a[0]), "r"(a[1]), "r"(a[2]), "r"(a[3]), "r"(b[0]), "r"(b[1]));
}

// ---------------- router ------------------------------------------------
__global__ void router_kernel(const float* __restrict__ x,
                              const float* __restrict__ rw,
                              const float* __restrict__ rb) {
    int t = blockIdx.x;
    int tid = threadIdx.x;
    float acc[EE];
#pragma unroll
    for (int e = 0; e < EE; e++) acc[e] = 0.f;
    const float* xr = x + (size_t)t * HH;
    for (int h = tid; h < HH; h += 128) {
        float xv = xr[h];
#pragma unroll
        for (int e = 0; e < EE; e++) acc[e] = fmaf(xv, rw[e * HH + h], acc[e]);
    }
#pragma unroll
    for (int e = 0; e < EE; e++) {
#pragma unroll
        for (int o = 16; o > 0; o >>= 1) acc[e] += __shfl_xor_sync(0xffffffffu, acc[e], o);
    }
    __shared__ float sl[4][EE];
    int w = tid >> 5;
    if ((tid & 31) == 0) {
#pragma unroll
        for (int e = 0; e < EE; e++) sl[w][e] = acc[e];
    }
    __syncthreads();
    if (tid == 0) {
        float lg[EE];
        float mx = -1e30f;
#pragma unroll
        for (int e = 0; e < EE; e++) {
            lg[e] = sl[0][e] + sl[1][e] + sl[2][e] + sl[3][e] + rb[e];
            mx = fmaxf(mx, lg[e]);
        }
        float p[EE];
#pragma unroll
        for (int e = 0; e < EE; e++) p[e] = __expf(lg[e] - mx);
        bool used[EE];
#pragma unroll
        for (int e = 0; e < EE; e++) used[e] = false;
        int sel[KTOP]; float pv[KTOP]; float psum = 0.f;
        for (int k = 0; k < KTOP; k++) {
            int best = 0; float bv = -1.f;
            for (int e = 0; e < EE; e++)
                if (!used[e] && p[e] > bv) { bv = p[e]; best = e; }
            used[best] = true; sel[k] = best; pv[k] = bv; psum += bv;
        }
        float inv = 1.f / psum;
        for (int k = 0; k < KTOP; k++) {
            g_tidx[t * 4 + k] = sel[k];
            g_tw[t * 4 + k]   = pv[k] * inv;
        }
    }
}

// ---------------- deterministic grouping --------------------------------
__global__ void group_kernel() {
    __shared__ unsigned char eid[NROWS];
    __shared__ int base[EE];
    int tid = threadIdx.x;
    for (int i = tid; i < NROWS; i += blockDim.x) eid[i] = (unsigned char)g_tidx[i];
    __syncthreads();
    if (tid == 0) {
        int cnt[EE];
        for (int e = 0; e < EE; e++) cnt[e] = 0;
        for (int i = 0; i < NROWS; i++) cnt[eid[i]]++;
        int s = 0;
        for (int e = 0; e < EE; e++) { base[e] = s; g_offs[e] = s; s += cnt[e]; }
        g_offs[EE] = s;
    }
    __syncthreads();
    if (tid < EE) {
        int cur = base[tid];
        for (int i = 0; i < NROWS; i++) {
            if (eid[i] == (unsigned char)tid) {
                g_pos[i] = cur;
                g_rowtok[cur] = i >> 2;
                g_roww[cur] = g_tw[i];
                cur++;
            }
        }
    }
}

// ---------------- grouped GEMM ------------------------------------------
// A (activations): LDG->cvt.rna->STS, double-buffered smem (tf32 in smem)
// B (weights):     cp.async raw fp32, 3-stage ring; cvt.rna on fragments
// One __syncthreads per K-tile. 2 CTAs/SM.
template<int MODE>
__global__ __launch_bounds__(256, 2)
void moe_gemm(const float* __restrict__ Xin, const float* __restrict__ W,
              const float* __restrict__ Bias) {
    const int e = blockIdx.z;
    const int gbase = g_offs[e];
    const int Me = g_offs[e + 1] - gbase;
    const int m0 = blockIdx.y * BM;
    if (m0 >= Me) return;
    const int n0 = blockIdx.x * BN;

    const float* X = (MODE == 2) ? (const float*)g_gate : Xin;

    extern __shared__ char smraw[];
    const uint32_t sbase = smem_u32(smraw);
    const uint32_t bring = sbase + 2 * A_BYTES;
    const int tid = threadIdx.x;
    const int lane = tid & 31;
    const int warp = tid >> 5;
    const int wm = warp >> 2;                  // 0..1
    const int wn = warp & 3;                   // 0..3

    float acc[4][5][4];
#pragma unroll
    for (int i = 0; i < 4; i++)
#pragma unroll
        for (int j = 0; j < 5; j++)
#pragma unroll
            for (int q = 0; q < 4; q++) acc[i][j][q] = 0.f;

    // ---- A staging coords: 4 float4 per thread ----
    const float* ga[4]; uint32_t sa[4]; bool va[4];
#pragma unroll
    for (int j = 0; j < 4; j++) {
        int f4 = tid + j * 256;
        int row = f4 >> 3, c4 = f4 & 7;
        va[j] = (m0 + row) < Me;
        sa[j] = SWZ((uint32_t)(row * 128 + c4 * 16));
        if (va[j]) {
            if (MODE == 2) ga[j] = X + (size_t)(gbase + m0 + row) * II + c4 * 4;
            else           ga[j] = X + (size_t)g_rowtok[gbase + m0 + row] * HH + c4 * 4;
        } else ga[j] = X;
    }
    // ---- B staging coords: 5 x cp.async 16B per thread ----
    const float* gb[5]; uint32_t sbo[5];
#pragma unroll
    for (int j = 0; j < 5; j++) {
        int f4 = tid + j * 256;
        int row = f4 >> 3, c4 = f4 & 7;
        sbo[j] = SWZ((uint32_t)(row * 128 + c4 * 16));
        gb[j] = W + (size_t)e * HH * II + (size_t)(n0 + row) * HH + c4 * 4;
    }

    // ---- ldmatrix lane constants ----
    const int at = lane >> 3;
    const int arow = wm * 64 + (at & 1) * 8 + (lane & 7);
    const int acol = (at >> 1) * 16;
    const int bt = lane >> 3;
    const int brow = wn * 40 + (bt >> 1) * 8 + (lane & 7);
    const int bcol = (bt & 1) * 16;
    const int brow2 = wn * 40 + 32 + (lane & 7);
    const int bcol2 = ((lane >> 3) & 1) * 16;

    // ---- prologue ----
    float4 ra[4];
#pragma unroll
    for (int j = 0; j < 4; j++)
        ra[j] = va[j] ? *(const float4*)(ga[j]) : make_float4(0.f, 0.f, 0.f, 0.f);
#pragma unroll
    for (int s = 0; s < 2; s++) {
        uint32_t bb = bring + s * B_BYTES;
#pragma unroll
        for (int j = 0; j < 5; j++)
            CP_ASYNC16(bb + sbo[j], gb[j] + s * BK);
        CP_COMMIT();
    }

    int bidx = 2;   // next B stage index to fill (kt+2) % 3, starts at 2
#pragma unroll 1
    for (int kt = 0; kt < NKT; ++kt) {
        CP_WAIT1();                              // B(kt) landed (this thread)
        uint32_t abase = sbase + (kt & 1) * A_BYTES;
#pragma unroll
        for (int j = 0; j < 4; j++)
            STS128(abase + sa[j], f2tf(ra[j].x), f2tf(ra[j].y), f2tf(ra[j].z), f2tf(ra[j].w));
        __syncthreads();                         // publish A(kt)+B(kt); frees bufs
        if (kt + 1 < NKT) {
            int k0 = (kt + 1) * BK;
#pragma unroll
            for (int j = 0; j < 4; j++)
                if (va[j]) ra[j] = *(const float4*)(ga[j] + k0);
        }
        if (kt + 2 < NKT) {
            uint32_t bb = bring + bidx * B_BYTES;
            int k0 = (kt + 2) * BK;
#pragma unroll
            for (int j = 0; j < 5; j++)
                CP_ASYNC16(bb + sbo[j], gb[j] + k0);
            bidx = (bidx + 1 == NSTB) ? 0 : bidx + 1;
        }
        CP_COMMIT();                             // keep group counting uniform

        uint32_t bbase = bring + (kt % 3) * B_BYTES;
#pragma unroll
        for (int kk = 0; kk < 32; kk += 8) {
            unsigned af[4][4];
#pragma unroll
            for (int mt = 0; mt < 4; mt++)
                ldsm4(af[mt], abase + SWZ((uint32_t)((arow + mt * 16) * 128 + kk * 4 + acol)));
            unsigned bf[5][2];
            ldsm4(&bf[0][0], bbase + SWZ((uint32_t)(brow * 128 + kk * 4 + bcol)));
            ldsm4(&bf[2][0], bbase + SWZ((uint32_t)((brow + 16) * 128 + kk * 4 + bcol)));
            ldsm2(&bf[4][0], bbase + SWZ((uint32_t)(brow2 * 128 + kk * 4 + bcol2)));
#pragma unroll
            for (int nt = 0; nt < 5; nt++) {
                bf[nt][0] = f2tf_u(bf[nt][0]);
                bf[nt][1] = f2tf_u(bf[nt][1]);
            }
#pragma unroll
            for (int mt = 0; mt < 4; mt++)
#pragma unroll
                for (int nt = 0; nt < 5; nt++)
                    mma8(acc[mt][nt], af[mt], bf[nt]);
        }
        __syncthreads();                         // A(kt)/B(kt) done before refill
    }

    // ---- epilogue ----
#pragma unroll
    for (int mt = 0; mt < 4; mt++) {
        int rloc0 = wm * 64 + mt * 16 + (lane >> 2);
#pragma unroll
        for (int half = 0; half < 2; half++) {
            int r = m0 + rloc0 + half * 8;
            if (r >= Me) continue;
            size_t orow = (size_t)(gbase + r) * (size_t)((MODE == 2) ? HH : II);
            float* Out = (MODE == 0) ? g_gate : (MODE == 1) ? g_up : g_dn;
            float wgt = (MODE == 2) ? g_roww[gbase + r] : 1.f;
#pragma unroll
            for (int nt = 0; nt < 5; nt++) {
                int col = n0 + wn * 40 + nt * 8 + (lane & 3) * 2;
                float v0 = acc[mt][nt][half * 2 + 0] + Bias[e * HH + col];
                float v1 = acc[mt][nt][half * 2 + 1] + Bias[e * HH + col + 1];
                if (MODE == 2) { v0 *= wgt; v1 *= wgt; }
                Out[orow + col]     = v0;
                Out[orow + col + 1] = v1;
            }
        }
    }
}

// ---------------- clipped SwiGLU ----------------------------------------
__global__ void act_kernel() {
    size_t idx = ((size_t)blockIdx.x * 256 + threadIdx.x) * 4;
    float4 g = *(const float4*)&g_gate[idx];
    float4 u = *(const float4*)&g_up[idx];
    float gv[4] = {g.x, g.y, g.z, g.w};
    float uv[4] = {u.x, u.y, u.z, u.w};
    float r[4];
#pragma unroll
    for (int i = 0; i < 4; i++) {
        float gg = fminf(gv[i], LIMIT);
        float uu = fminf(fmaxf(uv[i], -LIMIT), LIMIT);
        float s = 1.f / (1.f + __expf(-ALPHA * gg));
        r[i] = (uu + 1.f) * (gg * s);
    }
    *(float4*)&g_gate[idx] = make_float4(r[0], r[1], r[2], r[3]);
}

// ---------------- per-token fixed-order combine -------------------------
__global__ void combine_kernel(float* __restrict__ y) {
    int t = blockIdx.x;
    const float* r0 = g_dn + (size_t)g_pos[t * 4 + 0] * HH;
    const float* r1 = g_dn + (size_t)g_pos[t * 4 + 1] * HH;
    const float* r2 = g_dn + (size_t)g_pos[t * 4 + 2] * HH;
    const float* r3 = g_dn + (size_t)g_pos[t * 4 + 3] * HH;
    float* yo = y + (size_t)t * HH;
    for (int c = threadIdx.x * 4; c < HH; c += 256 * 4) {
        float4 a = *(const float4*)(r0 + c);
        float4 b = *(const float4*)(r1 + c);
        float4 d = *(const float4*)(r2 + c);
        float4 f = *(const float4*)(r3 + c);
        *(float4*)(yo + c) = make_float4(a.x + b.x + d.x + f.x, a.y + b.y + d.y + f.y,
                                         a.z + b.z + d.z + f.z, a.w + b.w + d.w + f.w);
    }
}

// ---------------- launch ------------------------------------------------
extern "C" void kernel_launch(void* const* d_in, const int* in_sizes, int n_in,
                              void* d_out, int out_size) {
    const float* x  = (const float*)d_in[0];
    const float* rw = (const float*)d_in[1];
    const float* rb = (const float*)d_in[2];
    const float* w1 = (const float*)d_in[3];
    const float* b1 = (const float*)d_in[4];
    const float* w3 = (const float*)d_in[5];
    const float* b3 = (const float*)d_in[6];
    const float* w2 = (const float*)d_in[7];
    const float* b2 = (const float*)d_in[8];
    float* y = (float*)d_out;

    cudaFuncSetAttribute(moe_gemm<0>, cudaFuncAttributeMaxDynamicSharedMemorySize, SMEM_BYTES);
    cudaFuncSetAttribute(moe_gemm<1>, cudaFuncAttributeMaxDynamicSharedMemorySize, SMEM_BYTES);
    cudaFuncSetAttribute(moe_gemm<2>, cudaFuncAttributeMaxDynamicSharedMemorySize, SMEM_BYTES);

    router_kernel<<<TT, 128>>>(x, rw, rb);
    group_kernel<<<1, 256>>>();

    dim3 ggrid(HH / BN, 8, EE);   // (18, 8, 16)
    moe_gemm<0><<<ggrid, 256, SMEM_BYTES>>>(x, w1, b1);
    moe_gemm<1><<<ggrid, 256, SMEM_BYTES>>>(x, w3, b3);

    act_kernel<<<(NROWS * II) / (256 * 4), 256>>>();

    moe_gemm<2><<<ggrid, 256, SMEM_BYTES>>>(nullptr, w2, b2);

    combine_kernel<<<TT, 256>>>(y);
}

// round 5
// speedup vs baseline: 1.4175x; 1.4175x over previous
#include <cuda_runtime.h>
#include <math.h>
#include <stdint.h>

#define TT 1024
#define HH 2880
#define II 2880
#define EE 16
#define KTOP 4
#define NROWS (TT * KTOP)
#define ALPHA 1.702f
#define LIMIT 7.0f

// GEMM tiling: BM=128, BN=160, BK=32 floats (128B rows, SW128)
#define BM 128
#define BN 160
#define BK 32
#define NKT (HH / BK)            // 90
#define A_BYTES (BM * BK * 4)    // 16384
#define B_BYTES (BN * BK * 4)    // 20480
#define NSTB 4
#define SMEM_BYTES (2 * A_BYTES + NSTB * B_BYTES)   // 114688

// ---------------- scratch -----------------------------------------------
__device__ float g_gate[(size_t)NROWS * II];
__device__ float g_up[(size_t)NROWS * II];
__device__ float g_dn[(size_t)NROWS * HH];
__device__ int   g_offs[EE + 1];
__device__ int   g_pos[NROWS];
__device__ int   g_rowtok[NROWS];
__device__ float g_roww[NROWS];
__device__ int   g_tidx[NROWS];
__device__ float g_tw[NROWS];

// ---------------- helpers -----------------------------------------------
__device__ __forceinline__ unsigned f2tf(float x) {
    unsigned r;
    asm("cvt.rna.tf32.f32 %0, %1;" : "=r"(r) : "f"(x));
    return r;
}
__device__ __forceinline__ unsigned f2tf_u(unsigned x) {
    unsigned r;
    asm("cvt.rna.tf32.f32 %0, %1;" : "=r"(r) : "f"(__uint_as_float(x)));
    return r;
}
__device__ __forceinline__ uint32_t smem_u32(const void* p) {
    uint32_t a;
    asm("{ .reg .u64 t; cvta.to.shared.u64 t, %1; cvt.u32.u64 %0, t; }" : "=r"(a) : "l"(p));
    return a;
}
__device__ __forceinline__ uint32_t SWZ(uint32_t off) {
    return off ^ ((off >> 3) & 0x70u);
}
#define STS128(addr, a, b, c, d)                                            \
    asm volatile("st.shared.v4.b32 [%0], {%1,%2,%3,%4};" ::"r"(addr),        \
                 "r"(a), "r"(b), "r"(c), "r"(d) : "memory")
#define CP_ASYNC16(dst, src)                                                \
    asm volatile("cp.async.cg.shared.global [%0], [%1], 16;" ::"r"(dst), "l"(src) : "memory")
#define CP_COMMIT() asm volatile("cp.async.commit_group;" ::: "memory")
#define CP_WAIT2()  asm volatile("cp.async.wait_group 2;" ::: "memory")

__device__ __forceinline__ void ldsm4(unsigned* r, uint32_t addr) {
    asm volatile("ldmatrix.sync.aligned.m8n8.x4.shared.b16 {%0,%1,%2,%3}, [%4];"
                 : "=r"(r[0]), "=r"(r[1]), "=r"(r[2]), "=r"(r[3]) : "r"(addr));
}
__device__ __forceinline__ void ldsm2(unsigned* r, uint32_t addr) {
    asm volatile("ldmatrix.sync.aligned.m8n8.x2.shared.b16 {%0,%1}, [%2];"
                 : "=r"(r[0]), "=r"(r[1]) : "r"(addr));
}
__device__ __forceinline__ void mma8(float* d, const unsigned* a, const unsigned* b) {
    asm volatile(
        "mma.sync.aligned.m16n8k8.row.col.f32.tf32.tf32.f32 "
        "{%0,%1,%2,%3}, {%4,%5,%6,%7}, {%8,%9}, {%0,%1,%2,%3};"
        : "+f"(d[0]), "+f"(d[1]), "+f"(d[2]), "+f"(d[3])
        : "r"(a[0]), "r"(a[1]), "r"(a[2]), "r"(a[3]), "r"(b[0]), "r"(b[1]));
}

// ---------------- router ------------------------------------------------
__global__ void router_kernel(const float* __restrict__ x,
                              const float* __restrict__ rw,
                              const float* __restrict__ rb) {
    int t = blockIdx.x;
    int tid = threadIdx.x;
    float acc[EE];
#pragma unroll
    for (int e = 0; e < EE; e++) acc[e] = 0.f;
    const float* xr = x + (size_t)t * HH;
    for (int h = tid; h < HH; h += 128) {
        float xv = xr[h];
#pragma unroll
        for (int e = 0; e < EE; e++) acc[e] = fmaf(xv, rw[e * HH + h], acc[e]);
    }
#pragma unroll
    for (int e = 0; e < EE; e++) {
#pragma unroll
        for (int o = 16; o > 0; o >>= 1) acc[e] += __shfl_xor_sync(0xffffffffu, acc[e], o);
    }
    __shared__ float sl[4][EE];
    int w = tid >> 5;
    if ((tid & 31) == 0) {
#pragma unroll
        for (int e = 0; e < EE; e++) sl[w][e] = acc[e];
    }
    __syncthreads();
    if (tid == 0) {
        float lg[EE];
        float mx = -1e30f;
#pragma unroll
        for (int e = 0; e < EE; e++) {
            lg[e] = sl[0][e] + sl[1][e] + sl[2][e] + sl[3][e] + rb[e];
            mx = fmaxf(mx, lg[e]);
        }
        float p[EE];
#pragma unroll
        for (int e = 0; e < EE; e++) p[e] = __expf(lg[e] - mx);
        bool used[EE];
#pragma unroll
        for (int e = 0; e < EE; e++) used[e] = false;
        int sel[KTOP]; float pv[KTOP]; float psum = 0.f;
        for (int k = 0; k < KTOP; k++) {
            int best = 0; float bv = -1.f;
            for (int e = 0; e < EE; e++)
                if (!used[e] && p[e] > bv) { bv = p[e]; best = e; }
            used[best] = true; sel[k] = best; pv[k] = bv; psum += bv;
        }
        float inv = 1.f / psum;
        for (int k = 0; k < KTOP; k++) {
            g_tidx[t * 4 + k] = sel[k];
            g_tw[t * 4 + k]   = pv[k] * inv;
        }
    }
}

// ---------------- deterministic grouping --------------------------------
__global__ void group_kernel() {
    __shared__ unsigned char eid[NROWS];
    __shared__ int base[EE];
    int tid = threadIdx.x;
    for (int i = tid; i < NROWS; i += blockDim.x) eid[i] = (unsigned char)g_tidx[i];
    __syncthreads();
    if (tid == 0) {
        int cnt[EE];
        for (int e = 0; e < EE; e++) cnt[e] = 0;
        for (int i = 0; i < NROWS; i++) cnt[eid[i]]++;
        int s = 0;
        for (int e = 0; e < EE; e++) { base[e] = s; g_offs[e] = s; s += cnt[e]; }
        g_offs[EE] = s;
    }
    __syncthreads();
    if (tid < EE) {
        int cur = base[tid];
        for (int i = 0; i < NROWS; i++) {
            if (eid[i] == (unsigned char)tid) {
                g_pos[i] = cur;
                g_rowtok[cur] = i >> 2;
                g_roww[cur] = g_tw[i];
                cur++;
            }
        }
    }
}

// ---------------- grouped GEMM ------------------------------------------
// A: LDG 1-tile-ahead -> cvt.rna -> STS (alternate buffer), tf32 in smem
// B: cp.async raw fp32, 4-stage ring, wait_group 2; cvt.rna on fragments
// ONE __syncthreads per K-tile. Natural occupancy (1 CTA/SM).
template<int MODE>
__global__ __launch_bounds__(256)
void moe_gemm(const float* __restrict__ Xin, const float* __restrict__ W,
              const float* __restrict__ Bias) {
    const int e = blockIdx.z;
    const int gbase = g_offs[e];
    const int Me = g_offs[e + 1] - gbase;
    const int m0 = blockIdx.y * BM;
    if (m0 >= Me) return;
    const int n0 = blockIdx.x * BN;

    const float* X = (MODE == 2) ? (const float*)g_gate : Xin;

    extern __shared__ char smraw[];
    const uint32_t sbase = smem_u32(smraw);
    const uint32_t bring = sbase + 2 * A_BYTES;
    const int tid = threadIdx.x;
    const int lane = tid & 31;
    const int warp = tid >> 5;
    const int wm = warp >> 2;                  // 0..1
    const int wn = warp & 3;                   // 0..3

    float acc[4][5][4];
#pragma unroll
    for (int i = 0; i < 4; i++)
#pragma unroll
        for (int j = 0; j < 5; j++)
#pragma unroll
            for (int q = 0; q < 4; q++) acc[i][j][q] = 0.f;

    // ---- A staging coords: 4 float4 per thread ----
    const float* ga[4]; uint32_t sa[4]; bool va[4];
#pragma unroll
    for (int j = 0; j < 4; j++) {
        int f4 = tid + j * 256;
        int row = f4 >> 3, c4 = f4 & 7;
        va[j] = (m0 + row) < Me;
        sa[j] = SWZ((uint32_t)(row * 128 + c4 * 16));
        if (va[j]) {
            if (MODE == 2) ga[j] = X + (size_t)(gbase + m0 + row) * II + c4 * 4;
            else           ga[j] = X + (size_t)g_rowtok[gbase + m0 + row] * HH + c4 * 4;
        } else ga[j] = X;
    }
    // ---- B staging coords: 5 x cp.async 16B per thread ----
    const float* gb[5]; uint32_t sbo[5];
#pragma unroll
    for (int j = 0; j < 5; j++) {
        int f4 = tid + j * 256;
        int row = f4 >> 3, c4 = f4 & 7;
        sbo[j] = SWZ((uint32_t)(row * 128 + c4 * 16));
        gb[j] = W + (size_t)e * HH * II + (size_t)(n0 + row) * HH + c4 * 4;
    }

    // ---- ldmatrix lane constants ----
    const int at = lane >> 3;
    const int arow = wm * 64 + (at & 1) * 8 + (lane & 7);
    const int acol = (at >> 1) * 16;
    const int bt = lane >> 3;
    const int brow = wn * 40 + (bt >> 1) * 8 + (lane & 7);
    const int bcol = (bt & 1) * 16;
    const int brow2 = wn * 40 + 32 + (lane & 7);
    const int bcol2 = ((lane >> 3) & 1) * 16;

    // ---- prologue: A(0) -> smem buf0; ra <- A(1); B(0..2) in flight ----
    float4 ra[4];
#pragma unroll
    for (int j = 0; j < 4; j++)
        ra[j] = va[j] ? *(const float4*)(ga[j]) : make_float4(0.f, 0.f, 0.f, 0.f);
#pragma unroll
    for (int j = 0; j < 4; j++)
        STS128(sbase + sa[j], f2tf(ra[j].x), f2tf(ra[j].y), f2tf(ra[j].z), f2tf(ra[j].w));
#pragma unroll
    for (int j = 0; j < 4; j++)
        ra[j] = va[j] ? *(const float4*)(ga[j] + BK) : make_float4(0.f, 0.f, 0.f, 0.f);
#pragma unroll
    for (int s = 0; s < 3; s++) {
        uint32_t bb = bring + s * B_BYTES;
#pragma unroll
        for (int j = 0; j < 5; j++)
            CP_ASYNC16(bb + sbo[j], gb[j] + s * BK);
        CP_COMMIT();
    }
    CP_WAIT2();            // B(0) complete
    __syncthreads();       // publish A(0), B(0)

#pragma unroll 1
    for (int kt = 0; kt < NKT; ++kt) {
        // 1. stage A(kt+1) into alternate buffer (regs loaded last iter)
        if (kt + 1 < NKT) {
            uint32_t abuf = sbase + ((kt + 1) & 1) * A_BYTES;
#pragma unroll
            for (int j = 0; j < 4; j++)
                STS128(abuf + sa[j], f2tf(ra[j].x), f2tf(ra[j].y), f2tf(ra[j].z), f2tf(ra[j].w));
        }
        // 2. prefetch A(kt+2) into regs
        if (kt + 2 < NKT) {
            int k0 = (kt + 2) * BK;
#pragma unroll
            for (int j = 0; j < 4; j++)
                if (va[j]) ra[j] = *(const float4*)(ga[j] + k0);
        }
        // 3. issue B(kt+3) into ring slot
        if (kt + 3 < NKT) {
            uint32_t bb = bring + ((kt + 3) & 3) * B_BYTES;
            int k0 = (kt + 3) * BK;
#pragma unroll
            for (int j = 0; j < 5; j++)
                CP_ASYNC16(bb + sbo[j], gb[j] + k0);
        }
        CP_COMMIT();       // uniform group count per iteration
        CP_WAIT2();        // completes B(kt+1); barrier below publishes it

        // 5. compute kt
        uint32_t abase = sbase + (kt & 1) * A_BYTES;
        uint32_t bbase = bring + (kt & 3) * B_BYTES;
#pragma unroll
        for (int kk = 0; kk < 32; kk += 8) {
            unsigned af[4][4];
#pragma unroll
            for (int mt = 0; mt < 4; mt++)
                ldsm4(af[mt], abase + SWZ((uint32_t)((arow + mt * 16) * 128 + kk * 4 + acol)));
            unsigned bf[5][2];
            ldsm4(&bf[0][0], bbase + SWZ((uint32_t)(brow * 128 + kk * 4 + bcol)));
            ldsm4(&bf[2][0], bbase + SWZ((uint32_t)((brow + 16) * 128 + kk * 4 + bcol)));
            ldsm2(&bf[4][0], bbase + SWZ((uint32_t)(brow2 * 128 + kk * 4 + bcol2)));
#pragma unroll
            for (int nt = 0; nt < 5; nt++) {
                bf[nt][0] = f2tf_u(bf[nt][0]);
                bf[nt][1] = f2tf_u(bf[nt][1]);
            }
#pragma unroll
            for (int mt = 0; mt < 4; mt++)
#pragma unroll
                for (int nt = 0; nt < 5; nt++)
                    mma8(acc[mt][nt], af[mt], bf[nt]);
        }
        __syncthreads();   // publish A(kt+1)+B(kt+1); free A(kt)/B-slot
    }

    // ---- epilogue ----
#pragma unroll
    for (int mt = 0; mt < 4; mt++) {
        int rloc0 = wm * 64 + mt * 16 + (lane >> 2);
#pragma unroll
        for (int half = 0; half < 2; half++) {
            int r = m0 + rloc0 + half * 8;
            if (r >= Me) continue;
            size_t orow = (size_t)(gbase + r) * (size_t)((MODE == 2) ? HH : II);
            float* Out = (MODE == 0) ? g_gate : (MODE == 1) ? g_up : g_dn;
            float wgt = (MODE == 2) ? g_roww[gbase + r] : 1.f;
#pragma unroll
            for (int nt = 0; nt < 5; nt++) {
                int col = n0 + wn * 40 + nt * 8 + (lane & 3) * 2;
                float v0 = acc[mt][nt][half * 2 + 0] + Bias[e * HH + col];
                float v1 = acc[mt][nt][half * 2 + 1] + Bias[e * HH + col + 1];
                if (MODE == 2) { v0 *= wgt; v1 *= wgt; }
                Out[orow + col]     = v0;
                Out[orow + col + 1] = v1;
            }
        }
    }
}

// ---------------- clipped SwiGLU ----------------------------------------
__global__ void act_kernel() {
    size_t idx = ((size_t)blockIdx.x * 256 + threadIdx.x) * 4;
    float4 g = *(const float4*)&g_gate[idx];
    float4 u = *(const float4*)&g_up[idx];
    float gv[4] = {g.x, g.y, g.z, g.w};
    float uv[4] = {u.x, u.y, u.z, u.w};
    float r[4];
#pragma unroll
    for (int i = 0; i < 4; i++) {
        float gg = fminf(gv[i], LIMIT);
        float uu = fminf(fmaxf(uv[i], -LIMIT), LIMIT);
        float s = 1.f / (1.f + __expf(-ALPHA * gg));
        r[i] = (uu + 1.f) * (gg * s);
    }
    *(float4*)&g_gate[idx] = make_float4(r[0], r[1], r[2], r[3]);
}

// ---------------- per-token fixed-order combine -------------------------
__global__ void combine_kernel(float* __restrict__ y) {
    int t = blockIdx.x;
    const float* r0 = g_dn + (size_t)g_pos[t * 4 + 0] * HH;
    const float* r1 = g_dn + (size_t)g_pos[t * 4 + 1] * HH;
    const float* r2 = g_dn + (size_t)g_pos[t * 4 + 2] * HH;
    const float* r3 = g_dn + (size_t)g_pos[t * 4 + 3] * HH;
    float* yo = y + (size_t)t * HH;
    for (int c = threadIdx.x * 4; c < HH; c += 256 * 4) {
        float4 a = *(const float4*)(r0 + c);
        float4 b = *(const float4*)(r1 + c);
        float4 d = *(const float4*)(r2 + c);
        float4 f = *(const float4*)(r3 + c);
        *(float4*)(yo + c) = make_float4(a.x + b.x + d.x + f.x, a.y + b.y + d.y + f.y,
                                         a.z + b.z + d.z + f.z, a.w + b.w + d.w + f.w);
    }
}

// ---------------- launch ------------------------------------------------
extern "C" void kernel_launch(void* const* d_in, const int* in_sizes, int n_in,
                              void* d_out, int out_size) {
    const float* x  = (const float*)d_in[0];
    const float* rw = (const float*)d_in[1];
    const float* rb = (const float*)d_in[2];
    const float* w1 = (const float*)d_in[3];
    const float* b1 = (const float*)d_in[4];
    const float* w3 = (const float*)d_in[5];
    const float* b3 = (const float*)d_in[6];
    const float* w2 = (const float*)d_in[7];
    const float* b2 = (const float*)d_in[8];
    float* y = (float*)d_out;

    cudaFuncSetAttribute(moe_gemm<0>, cudaFuncAttributeMaxDynamicSharedMemorySize, SMEM_BYTES);
    cudaFuncSetAttribute(moe_gemm<1>, cudaFuncAttributeMaxDynamicSharedMemorySize, SMEM_BYTES);
    cudaFuncSetAttribute(moe_gemm<2>, cudaFuncAttributeMaxDynamicSharedMemorySize, SMEM_BYTES);

    router_kernel<<<TT, 128>>>(x, rw, rb);
    group_kernel<<<1, 256>>>();

    dim3 ggrid(HH / BN, 8, EE);   // (18, 8, 16)
    moe_gemm<0><<<ggrid, 256, SMEM_BYTES>>>(x, w1, b1);
    moe_gemm<1><<<ggrid, 256, SMEM_BYTES>>>(x, w3, b3);

    act_kernel<<<(NROWS * II) / (256 * 4), 256>>>();

    moe_gemm<2><<<ggrid, 256, SMEM_BYTES>>>(nullptr, w2, b2);

    combine_kernel<<<TT, 256>>>(y);
}

// round 6
// speedup vs baseline: 1.5707x; 1.1081x over previous
#include <cuda_runtime.h>
#include <cuda_fp16.h>
#include <math.h>
#include <stdint.h>

#define TT 1024
#define HH 2880
#define II 2880
#define EE 16
#define KTOP 4
#define NROWS (TT * KTOP)
#define ALPHA 1.702f
#define LIMIT 7.0f

// Tiling: BM=128, BN=160, BK=32 (fp32 source). fp16 compute tiles are
// double-buffered PAIRED into 128B rows: byte = row*128 + buf*64 + k*2.
#define BM 128
#define BN 160
#define BK 32
#define NKT (HH / BK)              // 90
#define A16_BYTES (BM * 128)       // 16 KB  (both A fp16 buffers)
#define B16_BYTES (BN * 128)       // 20 KB  (both B fp16 buffers)
#define BRAW_BYTES (BN * BK * 4)   // 20 KB  per raw fp32 ring slot
#define NSTB 4
#define SMEM_BYTES (A16_BYTES + B16_BYTES + NSTB * BRAW_BYTES)  // 118784

// ---------------- scratch -----------------------------------------------
__device__ float g_gate[(size_t)NROWS * II];
__device__ float g_up[(size_t)NROWS * II];
__device__ float g_dn[(size_t)NROWS * HH];
__device__ int   g_offs[EE + 1];
__device__ int   g_pos[NROWS];
__device__ int   g_rowtok[NROWS];
__device__ float g_roww[NROWS];
__device__ int   g_tidx[NROWS];
__device__ float g_tw[NROWS];

// ---------------- helpers -----------------------------------------------
__device__ __forceinline__ unsigned pack_h2(float lo, float hi) {
    __half2 h = __floats2half2_rn(lo, hi);
    return *reinterpret_cast<unsigned*>(&h);
}
__device__ __forceinline__ uint32_t smem_u32(const void* p) {
    uint32_t a;
    asm("{ .reg .u64 t; cvta.to.shared.u64 t, %1; cvt.u32.u64 %0, t; }" : "=r"(a) : "l"(p));
    return a;
}
__device__ __forceinline__ uint32_t SWZ(uint32_t off) {
    return off ^ ((off >> 3) & 0x70u);
}
#define STS128(addr, a, b, c, d)                                            \
    asm volatile("st.shared.v4.b32 [%0], {%1,%2,%3,%4};" ::"r"(addr),        \
                 "r"(a), "r"(b), "r"(c), "r"(d) : "memory")
#define STS64(addr, a, b)                                                   \
    asm volatile("st.shared.v2.b32 [%0], {%1,%2};" ::"r"(addr), "r"(a), "r"(b) : "memory")
#define LDS128F(v, addr)                                                    \
    asm volatile("ld.shared.v4.f32 {%0,%1,%2,%3}, [%4];"                     \
                 : "=f"((v).x), "=f"((v).y), "=f"((v).z), "=f"((v).w) : "r"(addr))
#define CP_ASYNC16(dst, src)                                                \
    asm volatile("cp.async.cg.shared.global [%0], [%1], 16;" ::"r"(dst), "l"(src) : "memory")
#define CP_COMMIT() asm volatile("cp.async.commit_group;" ::: "memory")
#define CP_WAIT2()  asm volatile("cp.async.wait_group 2;" ::: "memory")

__device__ __forceinline__ void ldsm4(unsigned* r, uint32_t addr) {
    asm volatile("ldmatrix.sync.aligned.m8n8.x4.shared.b16 {%0,%1,%2,%3}, [%4];"
                 : "=r"(r[0]), "=r"(r[1]), "=r"(r[2]), "=r"(r[3]) : "r"(addr));
}
__device__ __forceinline__ void ldsm2(unsigned* r, uint32_t addr) {
    asm volatile("ldmatrix.sync.aligned.m8n8.x2.shared.b16 {%0,%1}, [%2];"
                 : "=r"(r[0]), "=r"(r[1]) : "r"(addr));
}
__device__ __forceinline__ void mma16(float* d, const unsigned* a, const unsigned* b) {
    asm volatile(
        "mma.sync.aligned.m16n8k16.row.col.f32.f16.f16.f32 "
        "{%0,%1,%2,%3}, {%4,%5,%6,%7}, {%8,%9}, {%0,%1,%2,%3};"
        : "+f"(d[0]), "+f"(d[1]), "+f"(d[2]), "+f"(d[3])
        : "r"(a[0]), "r"(a[1]), "r"(a[2]), "r"(a[3]), "r"(b[0]), "r"(b[1]));
}

// ---------------- router ------------------------------------------------
__global__ void router_kernel(const float* __restrict__ x,
                              const float* __restrict__ rw,
                              const float* __restrict__ rb) {
    int t = blockIdx.x;
    int tid = threadIdx.x;
    float acc[EE];
#pragma unroll
    for (int e = 0; e < EE; e++) acc[e] = 0.f;
    const float* xr = x + (size_t)t * HH;
    for (int h = tid; h < HH; h += 128) {
        float xv = xr[h];
#pragma unroll
        for (int e = 0; e < EE; e++) acc[e] = fmaf(xv, rw[e * HH + h], acc[e]);
    }
#pragma unroll
    for (int e = 0; e < EE; e++) {
#pragma unroll
        for (int o = 16; o > 0; o >>= 1) acc[e] += __shfl_xor_sync(0xffffffffu, acc[e], o);
    }
    __shared__ float sl[4][EE];
    int w = tid >> 5;
    if ((tid & 31) == 0) {
#pragma unroll
        for (int e = 0; e < EE; e++) sl[w][e] = acc[e];
    }
    __syncthreads();
    if (tid == 0) {
        float lg[EE];
        float mx = -1e30f;
#pragma unroll
        for (int e = 0; e < EE; e++) {
            lg[e] = sl[0][e] + sl[1][e] + sl[2][e] + sl[3][e] + rb[e];
            mx = fmaxf(mx, lg[e]);
        }
        float p[EE];
#pragma unroll
        for (int e = 0; e < EE; e++) p[e] = __expf(lg[e] - mx);
        bool used[EE];
#pragma unroll
        for (int e = 0; e < EE; e++) used[e] = false;
        int sel[KTOP]; float pv[KTOP]; float psum = 0.f;
        for (int k = 0; k < KTOP; k++) {
            int best = 0; float bv = -1.f;
            for (int e = 0; e < EE; e++)
                if (!used[e] && p[e] > bv) { bv = p[e]; best = e; }
            used[best] = true; sel[k] = best; pv[k] = bv; psum += bv;
        }
        float inv = 1.f / psum;
        for (int k = 0; k < KTOP; k++) {
            g_tidx[t * 4 + k] = sel[k];
            g_tw[t * 4 + k]   = pv[k] * inv;
        }
    }
}

// ---------------- deterministic grouping --------------------------------
__global__ void group_kernel() {
    __shared__ unsigned char eid[NROWS];
    __shared__ int base[EE];
    int tid = threadIdx.x;
    for (int i = tid; i < NROWS; i += blockDim.x) eid[i] = (unsigned char)g_tidx[i];
    __syncthreads();
    if (tid == 0) {
        int cnt[EE];
        for (int e = 0; e < EE; e++) cnt[e] = 0;
        for (int i = 0; i < NROWS; i++) cnt[eid[i]]++;
        int s = 0;
        for (int e = 0; e < EE; e++) { base[e] = s; g_offs[e] = s; s += cnt[e]; }
        g_offs[EE] = s;
    }
    __syncthreads();
    if (tid < EE) {
        int cur = base[tid];
        for (int i = 0; i < NROWS; i++) {
            if (eid[i] == (unsigned char)tid) {
                g_pos[i] = cur;
                g_rowtok[cur] = i >> 2;
                g_roww[cur] = g_tw[i];
                cur++;
            }
        }
    }
}

// ---------------- grouped GEMM (fp16 mma.m16n8k16, fp32 accumulate) ------
// A: LDG fp32 one tile ahead -> cvt f16x2 -> STS (paired double buffer)
// B: cp.async raw fp32 4-ring; per-thread smem convert to fp16 (own chunks)
// One __syncthreads per K-tile.
template<int MODE>
__global__ __launch_bounds__(256)
void moe_gemm(const float* __restrict__ Xin, const float* __restrict__ W,
              const float* __restrict__ Bias) {
    const int e = blockIdx.z;
    const int gbase = g_offs[e];
    const int Me = g_offs[e + 1] - gbase;
    const int m0 = blockIdx.y * BM;
    if (m0 >= Me) return;
    const int n0 = blockIdx.x * BN;

    const float* X = (MODE == 2) ? (const float*)g_gate : Xin;

    extern __shared__ char smraw[];
    const uint32_t a16 = smem_u32(smraw);
    const uint32_t b16 = a16 + A16_BYTES;
    const uint32_t bring = b16 + B16_BYTES;
    const int tid = threadIdx.x;
    const int lane = tid & 31;
    const int warp = tid >> 5;
    const int wm = warp >> 2;                  // 0..1
    const int wn = warp & 3;                   // 0..3

    float acc[4][5][4];
#pragma unroll
    for (int i = 0; i < 4; i++)
#pragma unroll
        for (int j = 0; j < 5; j++)
#pragma unroll
            for (int q = 0; q < 4; q++) acc[i][j][q] = 0.f;

    // ---- A staging: thread -> (row = tid>>1, khalf = tid&1), 16 floats ----
    const int arow_s = tid >> 1, khalf = tid & 1;
    const bool va = (m0 + arow_s) < Me;
    const float* ga;
    if (va) {
        if (MODE == 2) ga = X + (size_t)(gbase + m0 + arow_s) * II + khalf * 16;
        else           ga = X + (size_t)g_rowtok[gbase + m0 + arow_s] * HH + khalf * 16;
    } else ga = X;
    const uint32_t sa0 = SWZ((uint32_t)(arow_s * 128 + khalf * 32));
    const uint32_t sa1 = SWZ((uint32_t)(arow_s * 128 + khalf * 32 + 16));

    // ---- B raw staging (cp.async) + convert coords ----
    const float* gb[5]; uint32_t sbo[5]; uint32_t sc[5];
#pragma unroll
    for (int j = 0; j < 5; j++) {
        int f4 = tid + j * 256;
        int row = f4 >> 3, c4 = f4 & 7;
        sbo[j] = SWZ((uint32_t)(row * 128 + c4 * 16));
        sc[j]  = SWZ((uint32_t)(row * 128 + (c4 >> 1) * 16)) + (c4 & 1) * 8;
        gb[j] = W + (size_t)e * HH * II + (size_t)(n0 + row) * HH + c4 * 4;
    }

    // ---- ldsm base offsets (pre-swizzle; add kk2/buf then SWZ) ----
    uint32_t a_base[4];
#pragma unroll
    for (int mt = 0; mt < 4; mt++) {
        int row = wm * 64 + mt * 16 + (lane & 7) + ((lane >> 3) & 1) * 8;
        a_base[mt] = (uint32_t)(row * 128 + ((lane >> 4) & 1) * 16);
    }
    const int lane15 = lane & 15;
    uint32_t b_base0 = (uint32_t)((wn * 40 + (lane & 7) + ((lane >> 4) & 1) * 8) * 128 +
                                  ((lane >> 3) & 1) * 16);
    uint32_t b_base1 = b_base0 + 16 * 128;
    uint32_t b_base2 = (uint32_t)((wn * 40 + 32 + (lane15 & 7)) * 128 +
                                  ((lane15 >> 3) & 1) * 16);

    // ---- prologue ----
    float4 ra[4];
#pragma unroll
    for (int j = 0; j < 4; j++)
        ra[j] = va ? *(const float4*)(ga + j * 4) : make_float4(0.f, 0.f, 0.f, 0.f);
    {   // A(0) -> buf0
        unsigned u[8];
#pragma unroll
        for (int j = 0; j < 4; j++) {
            u[2 * j]     = pack_h2(ra[j].x, ra[j].y);
            u[2 * j + 1] = pack_h2(ra[j].z, ra[j].w);
        }
        STS128(a16 + sa0, u[0], u[1], u[2], u[3]);
        STS128(a16 + sa1, u[4], u[5], u[6], u[7]);
    }
#pragma unroll
    for (int j = 0; j < 4; j++)
        ra[j] = va ? *(const float4*)(ga + BK + j * 4) : make_float4(0.f, 0.f, 0.f, 0.f);
#pragma unroll
    for (int s = 0; s < 3; s++) {
        uint32_t bb = bring + s * BRAW_BYTES;
#pragma unroll
        for (int j = 0; j < 5; j++)
            CP_ASYNC16(bb + sbo[j], gb[j] + s * BK);
        CP_COMMIT();
    }
    CP_WAIT2();        // raw B(0) (own chunks) complete
    {   // convert B(0) -> fp16 buf0
        uint32_t rslot = bring;
#pragma unroll
        for (int j = 0; j < 5; j++) {
            float4 v; LDS128F(v, rslot + sbo[j]);
            STS64(b16 + sc[j], pack_h2(v.x, v.y), pack_h2(v.z, v.w));
        }
    }
    __syncthreads();   // publish A(0), B(0) fp16

#pragma unroll 1
    for (int kt = 0; kt < NKT; ++kt) {
        // 1. A(kt+1) regs -> fp16 alternate buffer
        if (kt + 1 < NKT) {
            unsigned u[8];
#pragma unroll
            for (int j = 0; j < 4; j++) {
                u[2 * j]     = pack_h2(ra[j].x, ra[j].y);
                u[2 * j + 1] = pack_h2(ra[j].z, ra[j].w);
            }
            uint32_t boff = ((kt + 1) & 1) * 64;
            STS128(a16 + (sa0 ^ boff), u[0], u[1], u[2], u[3]);
            STS128(a16 + (sa1 ^ boff), u[4], u[5], u[6], u[7]);
        }
        // 2. prefetch A(kt+2) into regs
        if (kt + 2 < NKT && va) {
            int k0 = (kt + 2) * BK;
#pragma unroll
            for (int j = 0; j < 4; j++)
                ra[j] = *(const float4*)(ga + k0 + j * 4);
        }
        // 3. cp.async raw B(kt+3)
        if (kt + 3 < NKT) {
            uint32_t bb = bring + ((kt + 3) & 3) * BRAW_BYTES;
            int k0 = (kt + 3) * BK;
#pragma unroll
            for (int j = 0; j < 5; j++)
                CP_ASYNC16(bb + sbo[j], gb[j] + k0);
        }
        CP_COMMIT();
        CP_WAIT2();    // raw B(kt+1) (own chunks) complete

        // 4. convert raw B(kt+1) -> fp16 alternate buffer (own chunks only)
        if (kt + 1 < NKT) {
            uint32_t rslot = bring + ((kt + 1) & 3) * BRAW_BYTES;
            uint32_t boff = ((kt + 1) & 1) * 64;
#pragma unroll
            for (int j = 0; j < 5; j++) {
                float4 v; LDS128F(v, rslot + sbo[j]);
                STS64(b16 + (sc[j] ^ boff), pack_h2(v.x, v.y), pack_h2(v.z, v.w));
            }
        }

        // 5. compute kt from fp16 buffers (kt&1)
        {
            uint32_t boff = (kt & 1) * 64;
#pragma unroll
            for (int kk2 = 0; kk2 < 64; kk2 += 32) {
                unsigned af[4][4];
#pragma unroll
                for (int mt = 0; mt < 4; mt++)
                    ldsm4(af[mt], a16 + SWZ(a_base[mt] + kk2 + boff));
                unsigned t0[4], t1[4], t2[2];
                ldsm4(t0, b16 + SWZ(b_base0 + kk2 + boff));
                ldsm4(t1, b16 + SWZ(b_base1 + kk2 + boff));
                ldsm2(t2, b16 + SWZ(b_base2 + kk2 + boff));
#pragma unroll
                for (int mt = 0; mt < 4; mt++) {
                    mma16(acc[mt][0], af[mt], &t0[0]);
                    mma16(acc[mt][1], af[mt], &t0[2]);
                    mma16(acc[mt][2], af[mt], &t1[0]);
                    mma16(acc[mt][3], af[mt], &t1[2]);
                    mma16(acc[mt][4], af[mt], t2);
                }
            }
        }
        __syncthreads();   // publish A(kt+1)+B(kt+1); free old buffers
    }

    // ---- epilogue ----
#pragma unroll
    for (int mt = 0; mt < 4; mt++) {
        int rloc0 = wm * 64 + mt * 16 + (lane >> 2);
#pragma unroll
        for (int half = 0; half < 2; half++) {
            int r = m0 + rloc0 + half * 8;
            if (r >= Me) continue;
            size_t orow = (size_t)(gbase + r) * (size_t)((MODE == 2) ? HH : II);
            float* Out = (MODE == 0) ? g_gate : (MODE == 1) ? g_up : g_dn;
            float wgt = (MODE == 2) ? g_roww[gbase + r] : 1.f;
#pragma unroll
            for (int nt = 0; nt < 5; nt++) {
                int col = n0 + wn * 40 + nt * 8 + (lane & 3) * 2;
                float v0 = acc[mt][nt][half * 2 + 0] + Bias[e * HH + col];
                float v1 = acc[mt][nt][half * 2 + 1] + Bias[e * HH + col + 1];
                if (MODE == 2) { v0 *= wgt; v1 *= wgt; }
                Out[orow + col]     = v0;
                Out[orow + col + 1] = v1;
            }
        }
    }
}

// ---------------- clipped SwiGLU ----------------------------------------
__global__ void act_kernel() {
    size_t idx = ((size_t)blockIdx.x * 256 + threadIdx.x) * 4;
    float4 g = *(const float4*)&g_gate[idx];
    float4 u = *(const float4*)&g_up[idx];
    float gv[4] = {g.x, g.y, g.z, g.w};
    float uv[4] = {u.x, u.y, u.z, u.w};
    float r[4];
#pragma unroll
    for (int i = 0; i < 4; i++) {
        float gg = fminf(gv[i], LIMIT);
        float uu = fminf(fmaxf(uv[i], -LIMIT), LIMIT);
        float s = 1.f / (1.f + __expf(-ALPHA * gg));
        r[i] = (uu + 1.f) * (gg * s);
    }
    *(float4*)&g_gate[idx] = make_float4(r[0], r[1], r[2], r[3]);
}

// ---------------- per-token fixed-order combine -------------------------
__global__ void combine_kernel(float* __restrict__ y) {
    int t = blockIdx.x;
    const float* r0 = g_dn + (size_t)g_pos[t * 4 + 0] * HH;
    const float* r1 = g_dn + (size_t)g_pos[t * 4 + 1] * HH;
    const float* r2 = g_dn + (size_t)g_pos[t * 4 + 2] * HH;
    const float* r3 = g_dn + (size_t)g_pos[t * 4 + 3] * HH;
    float* yo = y + (size_t)t * HH;
    for (int c = threadIdx.x * 4; c < HH; c += 256 * 4) {
        float4 a = *(const float4*)(r0 + c);
        float4 b = *(const float4*)(r1 + c);
        float4 d = *(const float4*)(r2 + c);
        float4 f = *(const float4*)(r3 + c);
        *(float4*)(yo + c) = make_float4(a.x + b.x + d.x + f.x, a.y + b.y + d.y + f.y,
                                         a.z + b.z + d.z + f.z, a.w + b.w + d.w + f.w);
    }
}

// ---------------- launch ------------------------------------------------
extern "C" void kernel_launch(void* const* d_in, const int* in_sizes, int n_in,
                              void* d_out, int out_size) {
    const float* x  = (const float*)d_in[0];
    const float* rw = (const float*)d_in[1];
    const float* rb = (const float*)d_in[2];
    const float* w1 = (const float*)d_in[3];
    const float* b1 = (const float*)d_in[4];
    const float* w3 = (const float*)d_in[5];
    const float* b3 = (const float*)d_in[6];
    const float* w2 = (const float*)d_in[7];
    const float* b2 = (const float*)d_in[8];
    float* y = (float*)d_out;

    cudaFuncSetAttribute(moe_gemm<0>, cudaFuncAttributeMaxDynamicSharedMemorySize, SMEM_BYTES);
    cudaFuncSetAttribute(moe_gemm<1>, cudaFuncAttributeMaxDynamicSharedMemorySize, SMEM_BYTES);
    cudaFuncSetAttribute(moe_gemm<2>, cudaFuncAttributeMaxDynamicSharedMemorySize, SMEM_BYTES);

    router_kernel<<<TT, 128>>>(x, rw, rb);
    group_kernel<<<1, 256>>>();

    dim3 ggrid(HH / BN, 8, EE);   // (18, 8, 16)
    moe_gemm<0><<<ggrid, 256, SMEM_BYTES>>>(x, w1, b1);
    moe_gemm<1><<<ggrid, 256, SMEM_BYTES>>>(x, w3, b3);

    act_kernel<<<(NROWS * II) / (256 * 4), 256>>>();

    moe_gemm<2><<<ggrid, 256, SMEM_BYTES>>>(nullptr, w2, b2);

    combine_kernel<<<TT, 256>>>(y);
}

// round 7
// speedup vs baseline: 1.9448x; 1.2382x over previous
#include <cuda_runtime.h>
#include <cuda_fp16.h>
#include <math.h>
#include <stdint.h>

#define TT 1024
#define HH 2880
#define II 2880
#define EE 16
#define KTOP 4
#define NROWS (TT * KTOP)
#define ALPHA 1.702f
#define LIMIT 7.0f

// fp16 GEMM tiling: BM=128, BN=160, BK=32 halves (64B rows packed 2/atom)
#define BM 128
#define BN 160
#define BKH 32
#define NKT (HH / BKH)            // 90
#define A_ST (BM * 64)            // 8192 B per stage
#define B_ST (BN * 64)            // 10240 B per stage
#define STG (A_ST + B_ST)         // 18432
#define NST 4
#define SMEM_BYTES (NST * STG)    // 73728

// ---------------- scratch -----------------------------------------------
__device__ float  g_gate[(size_t)NROWS * II];
__device__ float  g_up[(size_t)NROWS * II];
__device__ float  g_dn[(size_t)NROWS * HH];
__device__ __half g_h16[(size_t)NROWS * II];     // act output (GEMM3 A)
__device__ __half g_x16[(size_t)TT * HH];        // x in fp16
__device__ __half g_w1h[(size_t)EE * II * HH];
__device__ __half g_w3h[(size_t)EE * II * HH];
__device__ __half g_w2h[(size_t)EE * HH * II];
__device__ int    g_offs[EE + 1];
__device__ int    g_pos[NROWS];
__device__ int    g_rowtok[NROWS];
__device__ float  g_roww[NROWS];
__device__ int    g_tidx[NROWS];
__device__ float  g_tw[NROWS];

// ---------------- helpers -----------------------------------------------
__device__ __forceinline__ unsigned pack_h2(float lo, float hi) {
    __half2 h = __floats2half2_rn(lo, hi);
    return *reinterpret_cast<unsigned*>(&h);
}
__device__ __forceinline__ uint32_t smem_u32(const void* p) {
    uint32_t a;
    asm("{ .reg .u64 t; cvta.to.shared.u64 t, %1; cvt.u32.u64 %0, t; }" : "=r"(a) : "l"(p));
    return a;
}
__device__ __forceinline__ uint32_t SWZ(uint32_t off) {
    return off ^ ((off >> 3) & 0x70u);
}
#define CP_ASYNC16(dst, src)                                                \
    asm volatile("cp.async.cg.shared.global [%0], [%1], 16;" ::"r"(dst), "l"(src) : "memory")
#define CP_COMMIT() asm volatile("cp.async.commit_group;" ::: "memory")
#define CP_WAIT2()  asm volatile("cp.async.wait_group 2;" ::: "memory")

__device__ __forceinline__ void ldsm4(unsigned* r, uint32_t addr) {
    asm volatile("ldmatrix.sync.aligned.m8n8.x4.shared.b16 {%0,%1,%2,%3}, [%4];"
                 : "=r"(r[0]), "=r"(r[1]), "=r"(r[2]), "=r"(r[3]) : "r"(addr));
}
__device__ __forceinline__ void ldsm2(unsigned* r, uint32_t addr) {
    asm volatile("ldmatrix.sync.aligned.m8n8.x2.shared.b16 {%0,%1}, [%2];"
                 : "=r"(r[0]), "=r"(r[1]) : "r"(addr));
}
__device__ __forceinline__ void mma16(float* d, const unsigned* a, const unsigned* b) {
    asm volatile(
        "mma.sync.aligned.m16n8k16.row.col.f32.f16.f16.f32 "
        "{%0,%1,%2,%3}, {%4,%5,%6,%7}, {%8,%9}, {%0,%1,%2,%3};"
        : "+f"(d[0]), "+f"(d[1]), "+f"(d[2]), "+f"(d[3])
        : "r"(a[0]), "r"(a[1]), "r"(a[2]), "r"(a[3]), "r"(b[0]), "r"(b[1]));
}

// ---------------- fp32 -> fp16 streaming convert -------------------------
__global__ void cvt16(const float* __restrict__ s, __half* __restrict__ d) {
    size_t i = ((size_t)blockIdx.x * 256 + threadIdx.x) * 8;
    float4 a = *(const float4*)(s + i);
    float4 b = *(const float4*)(s + i + 4);
    uint4 o;
    o.x = pack_h2(a.x, a.y);
    o.y = pack_h2(a.z, a.w);
    o.z = pack_h2(b.x, b.y);
    o.w = pack_h2(b.z, b.w);
    *(uint4*)((char*)d + i * 2) = o;
}

// ---------------- router ------------------------------------------------
__global__ void router_kernel(const float* __restrict__ x,
                              const float* __restrict__ rw,
                              const float* __restrict__ rb) {
    int t = blockIdx.x;
    int tid = threadIdx.x;
    float acc[EE];
#pragma unroll
    for (int e = 0; e < EE; e++) acc[e] = 0.f;
    const float* xr = x + (size_t)t * HH;
    for (int h = tid; h < HH; h += 128) {
        float xv = xr[h];
#pragma unroll
        for (int e = 0; e < EE; e++) acc[e] = fmaf(xv, rw[e * HH + h], acc[e]);
    }
#pragma unroll
    for (int e = 0; e < EE; e++) {
#pragma unroll
        for (int o = 16; o > 0; o >>= 1) acc[e] += __shfl_xor_sync(0xffffffffu, acc[e], o);
    }
    __shared__ float sl[4][EE];
    int w = tid >> 5;
    if ((tid & 31) == 0) {
#pragma unroll
        for (int e = 0; e < EE; e++) sl[w][e] = acc[e];
    }
    __syncthreads();
    if (tid == 0) {
        float lg[EE];
        float mx = -1e30f;
#pragma unroll
        for (int e = 0; e < EE; e++) {
            lg[e] = sl[0][e] + sl[1][e] + sl[2][e] + sl[3][e] + rb[e];
            mx = fmaxf(mx, lg[e]);
        }
        float p[EE];
#pragma unroll
        for (int e = 0; e < EE; e++) p[e] = __expf(lg[e] - mx);
        bool used[EE];
#pragma unroll
        for (int e = 0; e < EE; e++) used[e] = false;
        int sel[KTOP]; float pv[KTOP]; float psum = 0.f;
        for (int k = 0; k < KTOP; k++) {
            int best = 0; float bv = -1.f;
            for (int e = 0; e < EE; e++)
                if (!used[e] && p[e] > bv) { bv = p[e]; best = e; }
            used[best] = true; sel[k] = best; pv[k] = bv; psum += bv;
        }
        float inv = 1.f / psum;
        for (int k = 0; k < KTOP; k++) {
            g_tidx[t * 4 + k] = sel[k];
            g_tw[t * 4 + k]   = pv[k] * inv;
        }
    }
}

// ---------------- deterministic grouping --------------------------------
__global__ void group_kernel() {
    __shared__ unsigned char eid[NROWS];
    __shared__ int base[EE];
    int tid = threadIdx.x;
    for (int i = tid; i < NROWS; i += blockDim.x) eid[i] = (unsigned char)g_tidx[i];
    __syncthreads();
    if (tid == 0) {
        int cnt[EE];
        for (int e = 0; e < EE; e++) cnt[e] = 0;
        for (int i = 0; i < NROWS; i++) cnt[eid[i]]++;
        int s = 0;
        for (int e = 0; e < EE; e++) { base[e] = s; g_offs[e] = s; s += cnt[e]; }
        g_offs[EE] = s;
    }
    __syncthreads();
    if (tid < EE) {
        int cur = base[tid];
        for (int i = 0; i < NROWS; i++) {
            if (eid[i] == (unsigned char)tid) {
                g_pos[i] = cur;
                g_rowtok[cur] = i >> 2;
                g_roww[cur] = g_tw[i];
                cur++;
            }
        }
    }
}

// ---------------- grouped GEMM: pure fp16 cp.async pipeline --------------
// MODE 0: gate = gather(x16) @ w1h^T + b1  -> g_gate (fp32)
// MODE 1: up   = gather(x16) @ w3h^T + b3  -> g_up   (fp32)
// MODE 2: dn   = w * (h16 @ w2h^T + b2)    -> g_dn   (fp32)
template<int MODE>
__global__ __launch_bounds__(256)
void moe_gemm(const __half* __restrict__ Wh, const float* __restrict__ Bias) {
    const int e = blockIdx.z;
    const int gbase = g_offs[e];
    const int Me = g_offs[e + 1] - gbase;
    const int m0 = blockIdx.y * BM;
    if (m0 >= Me) return;
    const int n0 = blockIdx.x * BN;

    extern __shared__ char smraw[];
    const uint32_t sb = smem_u32(smraw);
    const int tid = threadIdx.x;
    const int lane = tid & 31;
    const int warp = tid >> 5;
    const int wm = warp >> 2;                  // 0..1
    const int wn = warp & 3;                   // 0..3

    float acc[4][5][4];
#pragma unroll
    for (int i = 0; i < 4; i++)
#pragma unroll
        for (int j = 0; j < 5; j++)
#pragma unroll
            for (int q = 0; q < 4; q++) acc[i][j][q] = 0.f;

    // ---- A cp.async chunks: 512 total, 2 per thread ----
    const __half* gA[2]; uint32_t sA[2];
#pragma unroll
    for (int j = 0; j < 2; j++) {
        int c = tid + j * 256;
        int row = c >> 2, kc = c & 3;
        int r = m0 + row;
        if (r >= Me) r = 0;                    // clamp: garbage-safe (row unstored)
        const __half* rowp;
        if (MODE == 2) rowp = g_h16 + (size_t)(gbase + r) * II;
        else           rowp = g_x16 + (size_t)g_rowtok[gbase + r] * HH;
        gA[j] = rowp + kc * 8;
        sA[j] = SWZ((uint32_t)((row >> 1) * 128 + (row & 1) * 64 + kc * 16));
    }
    // ---- B cp.async chunks: 640 total, 3 for tid<128 else 2 ----
    const __half* gB[3]; uint32_t sB[3];
#pragma unroll
    for (int j = 0; j < 3; j++) {
        int c = tid + j * 256;
        if (c > 639) c = 639;                  // dummy (unissued for j==2, tid>=128)
        int row = c >> 2, kc = c & 3;
        gB[j] = Wh + (size_t)e * HH * II + (size_t)(n0 + row) * HH + kc * 8;
        sB[j] = A_ST + SWZ((uint32_t)((row >> 1) * 128 + (row & 1) * 64 + kc * 16));
    }

#define ISSUE(st)                                                            \
    do {                                                                     \
        uint32_t _b = sb + ((st) & 3) * STG;                                 \
        int _k = (st) * BKH;                                                 \
        CP_ASYNC16(_b + sA[0], gA[0] + _k);                                  \
        CP_ASYNC16(_b + sA[1], gA[1] + _k);                                  \
        CP_ASYNC16(_b + sB[0], gB[0] + _k);                                  \
        CP_ASYNC16(_b + sB[1], gB[1] + _k);                                  \
        if (tid < 128) CP_ASYNC16(_b + sB[2], gB[2] + _k);                   \
    } while (0)

    // ---- ldsm fragment offsets (stage-relative, pre-swizzled) ----
    uint32_t aoff[2][4], b0off[2], b1off[2], b2off[2];
    {
        const int lane15 = lane & 15;
#pragma unroll
        for (int ks = 0; ks < 2; ks++) {
#pragma unroll
            for (int mt = 0; mt < 4; mt++) {
                int R = wm * 64 + mt * 16 + (lane & 7) + ((lane >> 3) & 1) * 8;
                int c = ks * 2 + ((lane >> 4) & 1);
                aoff[ks][mt] = SWZ((uint32_t)((R >> 1) * 128 + (R & 1) * 64 + c * 16));
            }
            int Rb = wn * 40 + (lane & 7) + ((lane >> 4) & 1) * 8;
            int cb = ks * 2 + ((lane >> 3) & 1);
            b0off[ks] = A_ST + SWZ((uint32_t)((Rb >> 1) * 128 + (Rb & 1) * 64 + cb * 16));
            int Rb1 = Rb + 16;
            b1off[ks] = A_ST + SWZ((uint32_t)((Rb1 >> 1) * 128 + (Rb1 & 1) * 64 + cb * 16));
            int Rb2 = wn * 40 + 32 + (lane15 & 7);
            int cb2 = ks * 2 + ((lane15 >> 3) & 1);
            b2off[ks] = A_ST + SWZ((uint32_t)((Rb2 >> 1) * 128 + (Rb2 & 1) * 64 + cb2 * 16));
        }
    }

    // ---- prologue: stages 0..2 in flight ----
    ISSUE(0); CP_COMMIT();
    ISSUE(1); CP_COMMIT();
    ISSUE(2); CP_COMMIT();

#pragma unroll 1
    for (int kt = 0; kt < NKT; ++kt) {
        CP_WAIT2();            // own chunks of stage kt complete
        __syncthreads();       // all chunks visible; prev compute done (slot free)
        if (kt + 3 < NKT) ISSUE(kt + 3);
        CP_COMMIT();

        uint32_t base = sb + (kt & 3) * STG;
#pragma unroll
        for (int ks = 0; ks < 2; ks++) {
            unsigned af[4][4];
#pragma unroll
            for (int mt = 0; mt < 4; mt++) ldsm4(af[mt], base + aoff[ks][mt]);
            unsigned t0[4], t1[4], t2[2];
            ldsm4(t0, base + b0off[ks]);
            ldsm4(t1, base + b1off[ks]);
            ldsm2(t2, base + b2off[ks]);
#pragma unroll
            for (int mt = 0; mt < 4; mt++) {
                mma16(acc[mt][0], af[mt], &t0[0]);
                mma16(acc[mt][1], af[mt], &t0[2]);
                mma16(acc[mt][2], af[mt], &t1[0]);
                mma16(acc[mt][3], af[mt], &t1[2]);
                mma16(acc[mt][4], af[mt], t2);
            }
        }
    }

    // ---- epilogue ----
#pragma unroll
    for (int mt = 0; mt < 4; mt++) {
        int rloc0 = wm * 64 + mt * 16 + (lane >> 2);
#pragma unroll
        for (int half = 0; half < 2; half++) {
            int r = m0 + rloc0 + half * 8;
            if (r >= Me) continue;
            size_t orow = (size_t)(gbase + r) * (size_t)((MODE == 2) ? HH : II);
            float* Out = (MODE == 0) ? g_gate : (MODE == 1) ? g_up : g_dn;
            float wgt = (MODE == 2) ? g_roww[gbase + r] : 1.f;
#pragma unroll
            for (int nt = 0; nt < 5; nt++) {
                int col = n0 + wn * 40 + nt * 8 + (lane & 3) * 2;
                float v0 = acc[mt][nt][half * 2 + 0] + Bias[e * HH + col];
                float v1 = acc[mt][nt][half * 2 + 1] + Bias[e * HH + col + 1];
                if (MODE == 2) { v0 *= wgt; v1 *= wgt; }
                Out[orow + col]     = v0;
                Out[orow + col + 1] = v1;
            }
        }
    }
#undef ISSUE
}

// ---------------- clipped SwiGLU -> fp16 h -------------------------------
__global__ void act_kernel() {
    size_t idx = ((size_t)blockIdx.x * 256 + threadIdx.x) * 4;
    float4 g = *(const float4*)&g_gate[idx];
    float4 u = *(const float4*)&g_up[idx];
    float gv[4] = {g.x, g.y, g.z, g.w};
    float uv[4] = {u.x, u.y, u.z, u.w};
    float r[4];
#pragma unroll
    for (int i = 0; i < 4; i++) {
        float gg = fminf(gv[i], LIMIT);
        float uu = fminf(fmaxf(uv[i], -LIMIT), LIMIT);
        float s = 1.f / (1.f + __expf(-ALPHA * gg));
        r[i] = (uu + 1.f) * (gg * s);
    }
    uint2 o;
    o.x = pack_h2(r[0], r[1]);
    o.y = pack_h2(r[2], r[3]);
    *(uint2*)((char*)g_h16 + idx * 2) = o;
}

// ---------------- per-token fixed-order combine -------------------------
__global__ void combine_kernel(float* __restrict__ y) {
    int t = blockIdx.x;
    const float* r0 = g_dn + (size_t)g_pos[t * 4 + 0] * HH;
    const float* r1 = g_dn + (size_t)g_pos[t * 4 + 1] * HH;
    const float* r2 = g_dn + (size_t)g_pos[t * 4 + 2] * HH;
    const float* r3 = g_dn + (size_t)g_pos[t * 4 + 3] * HH;
    float* yo = y + (size_t)t * HH;
    for (int c = threadIdx.x * 4; c < HH; c += 256 * 4) {
        float4 a = *(const float4*)(r0 + c);
        float4 b = *(const float4*)(r1 + c);
        float4 d = *(const float4*)(r2 + c);
        float4 f = *(const float4*)(r3 + c);
        *(float4*)(yo + c) = make_float4(a.x + b.x + d.x + f.x, a.y + b.y + d.y + f.y,
                                         a.z + b.z + d.z + f.z, a.w + b.w + d.w + f.w);
    }
}

// ---------------- launch ------------------------------------------------
extern "C" void kernel_launch(void* const* d_in, const int* in_sizes, int n_in,
                              void* d_out, int out_size) {
    const float* x  = (const float*)d_in[0];
    const float* rw = (const float*)d_in[1];
    const float* rb = (const float*)d_in[2];
    const float* w1 = (const float*)d_in[3];
    const float* b1 = (const float*)d_in[4];
    const float* w3 = (const float*)d_in[5];
    const float* b3 = (const float*)d_in[6];
    const float* w2 = (const float*)d_in[7];
    const float* b2 = (const float*)d_in[8];
    float* y = (float*)d_out;

    __half* x16p;  cudaGetSymbolAddress((void**)&x16p,  g_x16);
    __half* w1p;   cudaGetSymbolAddress((void**)&w1p,   g_w1h);
    __half* w3p;   cudaGetSymbolAddress((void**)&w3p,   g_w3h);
    __half* w2p;   cudaGetSymbolAddress((void**)&w2p,   g_w2h);

    cudaFuncSetAttribute(moe_gemm<0>, cudaFuncAttributeMaxDynamicSharedMemorySize, SMEM_BYTES);
    cudaFuncSetAttribute(moe_gemm<1>, cudaFuncAttributeMaxDynamicSharedMemorySize, SMEM_BYTES);
    cudaFuncSetAttribute(moe_gemm<2>, cudaFuncAttributeMaxDynamicSharedMemorySize, SMEM_BYTES);

    const size_t WSZ = (size_t)EE * II * HH;       // 132,710,400
    cvt16<<<(TT * HH) / 2048, 256>>>(x, x16p);     // 1440 blocks
    cvt16<<<WSZ / 2048, 256>>>(w1, w1p);           // 64800 blocks
    cvt16<<<WSZ / 2048, 256>>>(w3, w3p);
    cvt16<<<WSZ / 2048, 256>>>(w2, w2p);

    router_kernel<<<TT, 128>>>(x, rw, rb);
    group_kernel<<<1, 256>>>();

    dim3 ggrid(HH / BN, 8, EE);   // (18, 8, 16)
    moe_gemm<0><<<ggrid, 256, SMEM_BYTES>>>(w1p, b1);
    moe_gemm<1><<<ggrid, 256, SMEM_BYTES>>>(w3p, b3);

    act_kernel<<<(NROWS * II) / (256 * 4), 256>>>();

    moe_gemm<2><<<ggrid, 256, SMEM_BYTES>>>(w2p, b2);

    combine_kernel<<<TT, 256>>>(y);
}

// round 8
// speedup vs baseline: 2.0435x; 1.0508x over previous
#include <cuda_runtime.h>
#include <cuda_fp16.h>
#include <math.h>
#include <stdint.h>

#define TT 1024
#define HH 2880
#define II 2880
#define EE 16
#define KTOP 4
#define NROWS (TT * KTOP)
#define ALPHA 1.702f
#define LIMIT 7.0f

// fp16 GEMM tiling: BM=128, BN=160, BKH=64 halves (natural 128B SW128 rows)
#define BM 128
#define BN 160
#define BKH 64
#define NKT (HH / BKH)            // 45
#define A_ST (BM * 128)           // 16384 B per stage
#define B_ST (BN * 128)           // 20480 B per stage
#define STG (A_ST + B_ST)         // 36864
#define NST 4
#define SMEM_BYTES (NST * STG)    // 147456

// ---------------- scratch -----------------------------------------------
__device__ float  g_gate[(size_t)NROWS * II];
__device__ float  g_up[(size_t)NROWS * II];
__device__ float  g_dn[(size_t)NROWS * HH];
__device__ __half g_h16[(size_t)NROWS * II];     // act output (GEMM3 A)
__device__ __half g_x16[(size_t)TT * HH];        // x in fp16
__device__ __half g_w1h[(size_t)EE * II * HH];
__device__ __half g_w3h[(size_t)EE * II * HH];
__device__ __half g_w2h[(size_t)EE * HH * II];
__device__ int    g_offs[EE + 1];
__device__ int    g_pos[NROWS];
__device__ int    g_rowtok[NROWS];
__device__ float  g_roww[NROWS];
__device__ int    g_tidx[NROWS];
__device__ float  g_tw[NROWS];

// ---------------- helpers -----------------------------------------------
__device__ __forceinline__ unsigned pack_h2(float lo, float hi) {
    __half2 h = __floats2half2_rn(lo, hi);
    return *reinterpret_cast<unsigned*>(&h);
}
__device__ __forceinline__ uint32_t smem_u32(const void* p) {
    uint32_t a;
    asm("{ .reg .u64 t; cvta.to.shared.u64 t, %1; cvt.u32.u64 %0, t; }" : "=r"(a) : "l"(p));
    return a;
}
__device__ __forceinline__ uint32_t SWZ(uint32_t off) {
    return off ^ ((off >> 3) & 0x70u);
}
#define CP_ASYNC16(dst, src)                                                \
    asm volatile("cp.async.cg.shared.global [%0], [%1], 16;" ::"r"(dst), "l"(src) : "memory")
#define CP_COMMIT() asm volatile("cp.async.commit_group;" ::: "memory")
#define CP_WAIT2()  asm volatile("cp.async.wait_group 2;" ::: "memory")

__device__ __forceinline__ void ldsm4(unsigned* r, uint32_t addr) {
    asm volatile("ldmatrix.sync.aligned.m8n8.x4.shared.b16 {%0,%1,%2,%3}, [%4];"
                 : "=r"(r[0]), "=r"(r[1]), "=r"(r[2]), "=r"(r[3]) : "r"(addr));
}
__device__ __forceinline__ void ldsm2(unsigned* r, uint32_t addr) {
    asm volatile("ldmatrix.sync.aligned.m8n8.x2.shared.b16 {%0,%1}, [%2];"
                 : "=r"(r[0]), "=r"(r[1]) : "r"(addr));
}
__device__ __forceinline__ void mma16(float* d, const unsigned* a, const unsigned* b) {
    asm volatile(
        "mma.sync.aligned.m16n8k16.row.col.f32.f16.f16.f32 "
        "{%0,%1,%2,%3}, {%4,%5,%6,%7}, {%8,%9}, {%0,%1,%2,%3};"
        : "+f"(d[0]), "+f"(d[1]), "+f"(d[2]), "+f"(d[3])
        : "r"(a[0]), "r"(a[1]), "r"(a[2]), "r"(a[3]), "r"(b[0]), "r"(b[1]));
}

// ---------------- fp32 -> fp16 streaming convert -------------------------
__global__ void cvt16(const float* __restrict__ s, __half* __restrict__ d) {
    size_t i = ((size_t)blockIdx.x * 256 + threadIdx.x) * 8;
    float4 a = *(const float4*)(s + i);
    float4 b = *(const float4*)(s + i + 4);
    uint4 o;
    o.x = pack_h2(a.x, a.y);
    o.y = pack_h2(a.z, a.w);
    o.z = pack_h2(b.x, b.y);
    o.w = pack_h2(b.z, b.w);
    *(uint4*)((char*)d + i * 2) = o;
}

// ---------------- router ------------------------------------------------
__global__ void router_kernel(const float* __restrict__ x,
                              const float* __restrict__ rw,
                              const float* __restrict__ rb) {
    int t = blockIdx.x;
    int tid = threadIdx.x;
    float acc[EE];
#pragma unroll
    for (int e = 0; e < EE; e++) acc[e] = 0.f;
    const float* xr = x + (size_t)t * HH;
    for (int h = tid; h < HH; h += 128) {
        float xv = xr[h];
#pragma unroll
        for (int e = 0; e < EE; e++) acc[e] = fmaf(xv, rw[e * HH + h], acc[e]);
    }
#pragma unroll
    for (int e = 0; e < EE; e++) {
#pragma unroll
        for (int o = 16; o > 0; o >>= 1) acc[e] += __shfl_xor_sync(0xffffffffu, acc[e], o);
    }
    __shared__ float sl[4][EE];
    int w = tid >> 5;
    if ((tid & 31) == 0) {
#pragma unroll
        for (int e = 0; e < EE; e++) sl[w][e] = acc[e];
    }
    __syncthreads();
    if (tid == 0) {
        float lg[EE];
        float mx = -1e30f;
#pragma unroll
        for (int e = 0; e < EE; e++) {
            lg[e] = sl[0][e] + sl[1][e] + sl[2][e] + sl[3][e] + rb[e];
            mx = fmaxf(mx, lg[e]);
        }
        float p[EE];
#pragma unroll
        for (int e = 0; e < EE; e++) p[e] = __expf(lg[e] - mx);
        bool used[EE];
#pragma unroll
        for (int e = 0; e < EE; e++) used[e] = false;
        int sel[KTOP]; float pv[KTOP]; float psum = 0.f;
        for (int k = 0; k < KTOP; k++) {
            int best = 0; float bv = -1.f;
            for (int e = 0; e < EE; e++)
                if (!used[e] && p[e] > bv) { bv = p[e]; best = e; }
            used[best] = true; sel[k] = best; pv[k] = bv; psum += bv;
        }
        float inv = 1.f / psum;
        for (int k = 0; k < KTOP; k++) {
            g_tidx[t * 4 + k] = sel[k];
            g_tw[t * 4 + k]   = pv[k] * inv;
        }
    }
}

// ---------------- deterministic grouping --------------------------------
__global__ void group_kernel() {
    __shared__ unsigned char eid[NROWS];
    __shared__ int base[EE];
    int tid = threadIdx.x;
    for (int i = tid; i < NROWS; i += blockDim.x) eid[i] = (unsigned char)g_tidx[i];
    __syncthreads();
    if (tid == 0) {
        int cnt[EE];
        for (int e = 0; e < EE; e++) cnt[e] = 0;
        for (int i = 0; i < NROWS; i++) cnt[eid[i]]++;
        int s = 0;
        for (int e = 0; e < EE; e++) { base[e] = s; g_offs[e] = s; s += cnt[e]; }
        g_offs[EE] = s;
    }
    __syncthreads();
    if (tid < EE) {
        int cur = base[tid];
        for (int i = 0; i < NROWS; i++) {
            if (eid[i] == (unsigned char)tid) {
                g_pos[i] = cur;
                g_rowtok[cur] = i >> 2;
                g_roww[cur] = g_tw[i];
                cur++;
            }
        }
    }
}

// ---------------- grouped GEMM: fp16, BK=64, fragment pipelined ----------
template<int MODE>
__global__ __launch_bounds__(256)
void moe_gemm(const __half* __restrict__ Wh, const float* __restrict__ Bias) {
    const int e = blockIdx.z;
    const int gbase = g_offs[e];
    const int Me = g_offs[e + 1] - gbase;
    const int m0 = blockIdx.y * BM;
    if (m0 >= Me) return;
    const int n0 = blockIdx.x * BN;

    extern __shared__ char smraw[];
    const uint32_t sb = smem_u32(smraw);
    const int tid = threadIdx.x;
    const int lane = tid & 31;
    const int warp = tid >> 5;
    const int wm = warp >> 2;                  // 0..1
    const int wn = warp & 3;                   // 0..3

    float acc[4][5][4];
#pragma unroll
    for (int i = 0; i < 4; i++)
#pragma unroll
        for (int j = 0; j < 5; j++)
#pragma unroll
            for (int q = 0; q < 4; q++) acc[i][j][q] = 0.f;

    // ---- A cp.async chunks: 1024 total, 4 per thread ----
    const __half* gA[4]; uint32_t sA[4];
#pragma unroll
    for (int j = 0; j < 4; j++) {
        int c = tid + j * 256;
        int row = c >> 3, kc = c & 7;
        int r = m0 + row;
        if (r >= Me) r = 0;                    // clamp: garbage-safe (row unstored)
        const __half* rowp;
        if (MODE == 2) rowp = g_h16 + (size_t)(gbase + r) * II;
        else           rowp = g_x16 + (size_t)g_rowtok[gbase + r] * HH;
        gA[j] = rowp + kc * 8;
        sA[j] = SWZ((uint32_t)(row * 128 + kc * 16));
    }
    // ---- B cp.async chunks: 1280 total, 5 per thread ----
    const __half* gB[5]; uint32_t sB[5];
#pragma unroll
    for (int j = 0; j < 5; j++) {
        int c = tid + j * 256;
        int row = c >> 3, kc = c & 7;
        gB[j] = Wh + (size_t)e * HH * II + (size_t)(n0 + row) * HH + kc * 8;
        sB[j] = A_ST + SWZ((uint32_t)(row * 128 + kc * 16));
    }

#define ISSUE(st)                                                            \
    do {                                                                     \
        uint32_t _b = sb + ((st) & 3) * STG;                                 \
        int _k = (st) * BKH;                                                 \
        CP_ASYNC16(_b + sA[0], gA[0] + _k);                                  \
        CP_ASYNC16(_b + sA[1], gA[1] + _k);                                  \
        CP_ASYNC16(_b + sA[2], gA[2] + _k);                                  \
        CP_ASYNC16(_b + sA[3], gA[3] + _k);                                  \
        CP_ASYNC16(_b + sB[0], gB[0] + _k);                                  \
        CP_ASYNC16(_b + sB[1], gB[1] + _k);                                  \
        CP_ASYNC16(_b + sB[2], gB[2] + _k);                                  \
        CP_ASYNC16(_b + sB[3], gB[3] + _k);                                  \
        CP_ASYNC16(_b + sB[4], gB[4] + _k);                                  \
    } while (0)

    // ---- ldsm raw offsets + per-lane swizzle masks ----
    const uint32_t axorm = (uint32_t)((lane & 7) << 4);
    const int lane15 = lane & 15;
    const uint32_t b2xor = (uint32_t)((lane15 & 7) << 4);
    uint32_t araw[4];
#pragma unroll
    for (int mt = 0; mt < 4; mt++) {
        int R = wm * 64 + mt * 16 + (lane & 7) + ((lane >> 3) & 1) * 8;
        araw[mt] = (uint32_t)(R * 128 + ((lane >> 4) & 1) * 16);
    }
    const uint32_t braw0 = (uint32_t)(A_ST + (wn * 40 + (lane & 7) + ((lane >> 4) & 1) * 8) * 128 +
                                      ((lane >> 3) & 1) * 16);
    const uint32_t braw1 = braw0 + 16 * 128;
    const uint32_t braw2 = (uint32_t)(A_ST + (wn * 40 + 32 + (lane15 & 7)) * 128 +
                                      ((lane15 >> 3) & 1) * 16);

#define LOADF(buf, ks)                                                       \
    do {                                                                     \
        uint32_t _o = (uint32_t)((ks) * 32);                                 \
        ldsm4(af[buf][0], base + ((araw[0] + _o) ^ axorm));                  \
        ldsm4(af[buf][1], base + ((araw[1] + _o) ^ axorm));                  \
        ldsm4(af[buf][2], base + ((araw[2] + _o) ^ axorm));                  \
        ldsm4(af[buf][3], base + ((araw[3] + _o) ^ axorm));                  \
        ldsm4(bt0[buf], base + ((braw0 + _o) ^ axorm));                      \
        ldsm4(bt1[buf], base + ((braw1 + _o) ^ axorm));                      \
        ldsm2(bt2[buf], base + ((braw2 + _o) ^ b2xor));                      \
    } while (0)

    // ---- prologue: stages 0..2 in flight ----
    ISSUE(0); CP_COMMIT();
    ISSUE(1); CP_COMMIT();
    ISSUE(2); CP_COMMIT();

#pragma unroll 1
    for (int kt = 0; kt < NKT; ++kt) {
        CP_WAIT2();            // own chunks of stage kt complete
        __syncthreads();       // all chunks visible; prev compute done (slot free)
        if (kt + 3 < NKT) ISSUE(kt + 3);
        CP_COMMIT();

        uint32_t base = sb + (kt & 3) * STG;
        unsigned af[2][4][4], bt0[2][4], bt1[2][4], bt2[2][2];
        LOADF(0, 0);
#pragma unroll
        for (int ks = 0; ks < 4; ks++) {
            int cur = ks & 1, nxt = cur ^ 1;
            if (ks < 3) LOADF(nxt, ks + 1);
#pragma unroll
            for (int mt = 0; mt < 4; mt++) {
                mma16(acc[mt][0], af[cur][mt], &bt0[cur][0]);
                mma16(acc[mt][1], af[cur][mt], &bt0[cur][2]);
                mma16(acc[mt][2], af[cur][mt], &bt1[cur][0]);
                mma16(acc[mt][3], af[cur][mt], &bt1[cur][2]);
                mma16(acc[mt][4], af[cur][mt], bt2[cur]);
            }
        }
    }

    // ---- epilogue ----
#pragma unroll
    for (int mt = 0; mt < 4; mt++) {
        int rloc0 = wm * 64 + mt * 16 + (lane >> 2);
#pragma unroll
        for (int half = 0; half < 2; half++) {
            int r = m0 + rloc0 + half * 8;
            if (r >= Me) continue;
            size_t orow = (size_t)(gbase + r) * (size_t)((MODE == 2) ? HH : II);
            float* Out = (MODE == 0) ? g_gate : (MODE == 1) ? g_up : g_dn;
            float wgt = (MODE == 2) ? g_roww[gbase + r] : 1.f;
#pragma unroll
            for (int nt = 0; nt < 5; nt++) {
                int col = n0 + wn * 40 + nt * 8 + (lane & 3) * 2;
                float v0 = acc[mt][nt][half * 2 + 0] + Bias[e * HH + col];
                float v1 = acc[mt][nt][half * 2 + 1] + Bias[e * HH + col + 1];
                if (MODE == 2) { v0 *= wgt; v1 *= wgt; }
                Out[orow + col]     = v0;
                Out[orow + col + 1] = v1;
            }
        }
    }
#undef ISSUE
#undef LOADF
}

// ---------------- clipped SwiGLU -> fp16 h -------------------------------
__global__ void act_kernel() {
    size_t idx = ((size_t)blockIdx.x * 256 + threadIdx.x) * 4;
    float4 g = *(const float4*)&g_gate[idx];
    float4 u = *(const float4*)&g_up[idx];
    float gv[4] = {g.x, g.y, g.z, g.w};
    float uv[4] = {u.x, u.y, u.z, u.w};
    float r[4];
#pragma unroll
    for (int i = 0; i < 4; i++) {
        float gg = fminf(gv[i], LIMIT);
        float uu = fminf(fmaxf(uv[i], -LIMIT), LIMIT);
        float s = 1.f / (1.f + __expf(-ALPHA * gg));
        r[i] = (uu + 1.f) * (gg * s);
    }
    uint2 o;
    o.x = pack_h2(r[0], r[1]);
    o.y = pack_h2(r[2], r[3]);
    *(uint2*)((char*)g_h16 + idx * 2) = o;
}

// ---------------- per-token fixed-order combine -------------------------
__global__ void combine_kernel(float* __restrict__ y) {
    int t = blockIdx.x;
    const float* r0 = g_dn + (size_t)g_pos[t * 4 + 0] * HH;
    const float* r1 = g_dn + (size_t)g_pos[t * 4 + 1] * HH;
    const float* r2 = g_dn + (size_t)g_pos[t * 4 + 2] * HH;
    const float* r3 = g_dn + (size_t)g_pos[t * 4 + 3] * HH;
    float* yo = y + (size_t)t * HH;
    for (int c = threadIdx.x * 4; c < HH; c += 256 * 4) {
        float4 a = *(const float4*)(r0 + c);
        float4 b = *(const float4*)(r1 + c);
        float4 d = *(const float4*)(r2 + c);
        float4 f = *(const float4*)(r3 + c);
        *(float4*)(yo + c) = make_float4(a.x + b.x + d.x + f.x, a.y + b.y + d.y + f.y,
                                         a.z + b.z + d.z + f.z, a.w + b.w + d.w + f.w);
    }
}

// ---------------- launch ------------------------------------------------
extern "C" void kernel_launch(void* const* d_in, const int* in_sizes, int n_in,
                              void* d_out, int out_size) {
    const float* x  = (const float*)d_in[0];
    const float* rw = (const float*)d_in[1];
    const float* rb = (const float*)d_in[2];
    const float* w1 = (const float*)d_in[3];
    const float* b1 = (const float*)d_in[4];
    const float* w3 = (const float*)d_in[5];
    const float* b3 = (const float*)d_in[6];
    const float* w2 = (const float*)d_in[7];
    const float* b2 = (const float*)d_in[8];
    float* y = (float*)d_out;

    __half* x16p;  cudaGetSymbolAddress((void**)&x16p,  g_x16);
    __half* w1p;   cudaGetSymbolAddress((void**)&w1p,   g_w1h);
    __half* w3p;   cudaGetSymbolAddress((void**)&w3p,   g_w3h);
    __half* w2p;   cudaGetSymbolAddress((void**)&w2p,   g_w2h);

    cudaFuncSetAttribute(moe_gemm<0>, cudaFuncAttributeMaxDynamicSharedMemorySize, SMEM_BYTES);
    cudaFuncSetAttribute(moe_gemm<1>, cudaFuncAttributeMaxDynamicSharedMemorySize, SMEM_BYTES);
    cudaFuncSetAttribute(moe_gemm<2>, cudaFuncAttributeMaxDynamicSharedMemorySize, SMEM_BYTES);

    const size_t WSZ = (size_t)EE * II * HH;       // 132,710,400
    cvt16<<<(TT * HH) / 2048, 256>>>(x, x16p);     // 1440 blocks
    cvt16<<<WSZ / 2048, 256>>>(w1, w1p);           // 64800 blocks
    cvt16<<<WSZ / 2048, 256>>>(w3, w3p);
    cvt16<<<WSZ / 2048, 256>>>(w2, w2p);

    router_kernel<<<TT, 128>>>(x, rw, rb);
    group_kernel<<<1, 256>>>();

    dim3 ggrid(HH / BN, 8, EE);   // (18, 8, 16)
    moe_gemm<0><<<ggrid, 256, SMEM_BYTES>>>(w1p, b1);
    moe_gemm<1><<<ggrid, 256, SMEM_BYTES>>>(w3p, b3);

    act_kernel<<<(NROWS * II) / (256 * 4), 256>>>();

    moe_gemm<2><<<ggrid, 256, SMEM_BYTES>>>(w2p, b2);

    combine_kernel<<<TT, 256>>>(y);
}

// round 10
// speedup vs baseline: 2.1016x; 1.0284x over previous
#include <cuda_runtime.h>
#include <cuda_fp16.h>
#include <math.h>
#include <stdint.h>

#define TT 1024
#define HH 2880
#define II 2880
#define EE 16
#define KTOP 4
#define NROWS (TT * KTOP)
#define ALPHA 1.702f
#define LIMIT 7.0f

// fp16 GEMM tiling: BM=128, BN=160, BKH=64 halves (natural 128B SW128 rows)
#define BM 128
#define BN 160
#define BKH 64
#define NKT (HH / BKH)            // 45
#define A_ST (BM * 128)           // 16384 B per stage
#define B_ST (BN * 128)           // 20480 B per stage
#define STG (A_ST + B_ST)         // 36864
#define NST 5
#define SMEM_BYTES (NST * STG)    // 184320

// ---------------- scratch -----------------------------------------------
__device__ float  g_gate[(size_t)NROWS * II];
__device__ float  g_up[(size_t)NROWS * II];
__device__ float  g_dn[(size_t)NROWS * HH];
__device__ __half g_h16[(size_t)NROWS * II];     // act output (GEMM3 A)
__device__ __half g_x16[(size_t)TT * HH];        // x in fp16
__device__ __half g_w1h[(size_t)EE * II * HH];
__device__ __half g_w3h[(size_t)EE * II * HH];
__device__ __half g_w2h[(size_t)EE * HH * II];
__device__ int    g_offs[EE + 1];
__device__ int    g_pos[NROWS];
__device__ int    g_rowtok[NROWS];
__device__ float  g_roww[NROWS];
__device__ int    g_tidx[NROWS];
__device__ float  g_tw[NROWS];

// ---------------- helpers -----------------------------------------------
__device__ __forceinline__ unsigned pack_h2(float lo, float hi) {
    __half2 h = __floats2half2_rn(lo, hi);
    return *reinterpret_cast<unsigned*>(&h);
}
__device__ __forceinline__ uint32_t smem_u32(const void* p) {
    uint32_t a;
    asm("{ .reg .u64 t; cvta.to.shared.u64 t, %1; cvt.u32.u64 %0, t; }" : "=r"(a) : "l"(p));
    return a;
}
__device__ __forceinline__ uint32_t SWZ(uint32_t off) {
    return off ^ ((off >> 3) & 0x70u);
}
#define CP_ASYNC16(dst, src)                                                \
    asm volatile("cp.async.cg.shared.global [%0], [%1], 16;" ::"r"(dst), "l"(src) : "memory")
#define CP_COMMIT() asm volatile("cp.async.commit_group;" ::: "memory")
#define CP_WAIT2()  asm volatile("cp.async.wait_group 2;" ::: "memory")
#define CP_WAIT3()  asm volatile("cp.async.wait_group 3;" ::: "memory")

__device__ __forceinline__ void ldsm4(unsigned* r, uint32_t addr) {
    asm volatile("ldmatrix.sync.aligned.m8n8.x4.shared.b16 {%0,%1,%2,%3}, [%4];"
                 : "=r"(r[0]), "=r"(r[1]), "=r"(r[2]), "=r"(r[3]) : "r"(addr));
}
__device__ __forceinline__ void ldsm2(unsigned* r, uint32_t addr) {
    asm volatile("ldmatrix.sync.aligned.m8n8.x2.shared.b16 {%0,%1}, [%2];"
                 : "=r"(r[0]), "=r"(r[1]) : "r"(addr));
}
__device__ __forceinline__ void mma16(float* d, const unsigned* a, const unsigned* b) {
    asm volatile(
        "mma.sync.aligned.m16n8k16.row.col.f32.f16.f16.f32 "
        "{%0,%1,%2,%3}, {%4,%5,%6,%7}, {%8,%9}, {%0,%1,%2,%3};"
        : "+f"(d[0]), "+f"(d[1]), "+f"(d[2]), "+f"(d[3])
        : "r"(a[0]), "r"(a[1]), "r"(a[2]), "r"(a[3]), "r"(b[0]), "r"(b[1]));
}

// ---------------- fp32 -> fp16 streaming convert -------------------------
__global__ void cvt16(const float* __restrict__ s, __half* __restrict__ d) {
    size_t i = ((size_t)blockIdx.x * 256 + threadIdx.x) * 8;
    float4 a = *(const float4*)(s + i);
    float4 b = *(const float4*)(s + i + 4);
    uint4 o;
    o.x = pack_h2(a.x, a.y);
    o.y = pack_h2(a.z, a.w);
    o.z = pack_h2(b.x, b.y);
    o.w = pack_h2(b.z, b.w);
    *(uint4*)((char*)d + i * 2) = o;
}

// ---------------- router ------------------------------------------------
__global__ void router_kernel(const float* __restrict__ x,
                              const float* __restrict__ rw,
                              const float* __restrict__ rb) {
    int t = blockIdx.x;
    int tid = threadIdx.x;
    float acc[EE];
#pragma unroll
    for (int e = 0; e < EE; e++) acc[e] = 0.f;
    const float* xr = x + (size_t)t * HH;
    for (int h = tid; h < HH; h += 128) {
        float xv = xr[h];
#pragma unroll
        for (int e = 0; e < EE; e++) acc[e] = fmaf(xv, rw[e * HH + h], acc[e]);
    }
#pragma unroll
    for (int e = 0; e < EE; e++) {
#pragma unroll
        for (int o = 16; o > 0; o >>= 1) acc[e] += __shfl_xor_sync(0xffffffffu, acc[e], o);
    }
    __shared__ float sl[4][EE];
    int w = tid >> 5;
    if ((tid & 31) == 0) {
#pragma unroll
        for (int e = 0; e < EE; e++) sl[w][e] = acc[e];
    }
    __syncthreads();
    if (tid == 0) {
        float lg[EE];
        float mx = -1e30f;
#pragma unroll
        for (int e = 0; e < EE; e++) {
            lg[e] = sl[0][e] + sl[1][e] + sl[2][e] + sl[3][e] + rb[e];
            mx = fmaxf(mx, lg[e]);
        }
        float p[EE];
#pragma unroll
        for (int e = 0; e < EE; e++) p[e] = __expf(lg[e] - mx);
        bool used[EE];
#pragma unroll
        for (int e = 0; e < EE; e++) used[e] = false;
        int sel[KTOP]; float pv[KTOP]; float psum = 0.f;
        for (int k = 0; k < KTOP; k++) {
            int best = 0; float bv = -1.f;
            for (int e = 0; e < EE; e++)
                if (!used[e] && p[e] > bv) { bv = p[e]; best = e; }
            used[best] = true; sel[k] = best; pv[k] = bv; psum += bv;
        }
        float inv = 1.f / psum;
        for (int k = 0; k < KTOP; k++) {
            g_tidx[t * 4 + k] = sel[k];
            g_tw[t * 4 + k]   = pv[k] * inv;
        }
    }
}

// ---------------- deterministic grouping --------------------------------
__global__ void group_kernel() {
    __shared__ unsigned char eid[NROWS];
    __shared__ int base[EE];
    int tid = threadIdx.x;
    for (int i = tid; i < NROWS; i += blockDim.x) eid[i] = (unsigned char)g_tidx[i];
    __syncthreads();
    if (tid == 0) {
        int cnt[EE];
        for (int e = 0; e < EE; e++) cnt[e] = 0;
        for (int i = 0; i < NROWS; i++) cnt[eid[i]]++;
        int s = 0;
        for (int e = 0; e < EE; e++) { base[e] = s; g_offs[e] = s; s += cnt[e]; }
        g_offs[EE] = s;
    }
    __syncthreads();
    if (tid < EE) {
        int cur = base[tid];
        for (int i = 0; i < NROWS; i++) {
            if (eid[i] == (unsigned char)tid) {
                g_pos[i] = cur;
                g_rowtok[cur] = i >> 2;
                g_roww[cur] = g_tw[i];
                cur++;
            }
        }
    }
}

// ---------------- grouped GEMM: fp16, BK=64, mid-iter barrier, 5 stages --
template<int MODE>
__global__ __launch_bounds__(256)
void moe_gemm(const __half* __restrict__ Wh, const float* __restrict__ Bias) {
    const int e = blockIdx.z;
    const int gbase = g_offs[e];
    const int Me = g_offs[e + 1] - gbase;
    const int m0 = blockIdx.y * BM;
    if (m0 >= Me) return;
    const int n0 = blockIdx.x * BN;

    extern __shared__ char smraw[];
    const uint32_t sb = smem_u32(smraw);
    const int tid = threadIdx.x;
    const int lane = tid & 31;
    const int warp = tid >> 5;
    const int wm = warp >> 2;                  // 0..1
    const int wn = warp & 3;                   // 0..3

    float acc[4][5][4];
#pragma unroll
    for (int i = 0; i < 4; i++)
#pragma unroll
        for (int j = 0; j < 5; j++)
#pragma unroll
            for (int q = 0; q < 4; q++) acc[i][j][q] = 0.f;

    // ---- A cp.async chunks: 1024 total, 4 per thread ----
    const __half* gA[4]; uint32_t sA[4];
#pragma unroll
    for (int j = 0; j < 4; j++) {
        int c = tid + j * 256;
        int row = c >> 3, kc = c & 7;
        int r = m0 + row;
        if (r >= Me) r = 0;                    // clamp: garbage-safe (row unstored)
        const __half* rowp;
        if (MODE == 2) rowp = g_h16 + (size_t)(gbase + r) * II;
        else           rowp = g_x16 + (size_t)g_rowtok[gbase + r] * HH;
        gA[j] = rowp + kc * 8;
        sA[j] = SWZ((uint32_t)(row * 128 + kc * 16));
    }
    // ---- B cp.async chunks: 1280 total, 5 per thread ----
    const __half* gB[5]; uint32_t sB[5];
#pragma unroll
    for (int j = 0; j < 5; j++) {
        int c = tid + j * 256;
        int row = c >> 3, kc = c & 7;
        gB[j] = Wh + (size_t)e * HH * II + (size_t)(n0 + row) * HH + kc * 8;
        sB[j] = A_ST + SWZ((uint32_t)(row * 128 + kc * 16));
    }

#define ISSUE_AT(dstbase, st)                                                \
    do {                                                                     \
        uint32_t _b = (dstbase);                                             \
        int _k = (st) * BKH;                                                 \
        CP_ASYNC16(_b + sA[0], gA[0] + _k);                                  \
        CP_ASYNC16(_b + sA[1], gA[1] + _k);                                  \
        CP_ASYNC16(_b + sA[2], gA[2] + _k);                                  \
        CP_ASYNC16(_b + sA[3], gA[3] + _k);                                  \
        CP_ASYNC16(_b + sB[0], gB[0] + _k);                                  \
        CP_ASYNC16(_b + sB[1], gB[1] + _k);                                  \
        CP_ASYNC16(_b + sB[2], gB[2] + _k);                                  \
        CP_ASYNC16(_b + sB[3], gB[3] + _k);                                  \
        CP_ASYNC16(_b + sB[4], gB[4] + _k);                                  \
    } while (0)

    // ---- ldsm raw offsets + per-lane swizzle masks ----
    const uint32_t axorm = (uint32_t)((lane & 7) << 4);
    const int lane15 = lane & 15;
    const uint32_t b2xor = (uint32_t)((lane15 & 7) << 4);
    uint32_t araw[4];
#pragma unroll
    for (int mt = 0; mt < 4; mt++) {
        int R = wm * 64 + mt * 16 + (lane & 7) + ((lane >> 3) & 1) * 8;
        araw[mt] = (uint32_t)(R * 128 + ((lane >> 4) & 1) * 16);
    }
    const uint32_t braw0 = (uint32_t)(A_ST + (wn * 40 + (lane & 7) + ((lane >> 4) & 1) * 8) * 128 +
                                      ((lane >> 3) & 1) * 16);
    const uint32_t braw1 = braw0 + 16 * 128;
    const uint32_t braw2 = (uint32_t)(A_ST + (wn * 40 + 32 + (lane15 & 7)) * 128 +
                                      ((lane15 >> 3) & 1) * 16);

    unsigned af[4][4], bt0[2][4], bt1[2][4], bt2[2][2];

#define LOADA(bbase, ks)                                                     \
    do {                                                                     \
        uint32_t _o = (uint32_t)((ks) * 32);                                 \
        ldsm4(af[0], (bbase) + ((araw[0] + _o) ^ axorm));                    \
        ldsm4(af[1], (bbase) + ((araw[1] + _o) ^ axorm));                    \
        ldsm4(af[2], (bbase) + ((araw[2] + _o) ^ axorm));                    \
        ldsm4(af[3], (bbase) + ((araw[3] + _o) ^ axorm));                    \
    } while (0)
#define LOADB(buf, bbase, ks)                                                \
    do {                                                                     \
        uint32_t _o = (uint32_t)((ks) * 32);                                 \
        ldsm4(bt0[buf], (bbase) + ((braw0 + _o) ^ axorm));                   \
        ldsm4(bt1[buf], (bbase) + ((braw1 + _o) ^ axorm));                   \
        ldsm2(bt2[buf], (bbase) + ((braw2 + _o) ^ b2xor));                   \
    } while (0)
#define MMAS(buf)                                                            \
    do {                                                                     \
        _Pragma("unroll")                                                    \
        for (int mt = 0; mt < 4; mt++) {                                     \
            mma16(acc[mt][0], af[mt], &bt0[buf][0]);                         \
            mma16(acc[mt][1], af[mt], &bt0[buf][2]);                         \
            mma16(acc[mt][2], af[mt], &bt1[buf][0]);                         \
            mma16(acc[mt][3], af[mt], &bt1[buf][2]);                         \
            mma16(acc[mt][4], af[mt], bt2[buf]);                             \
        }                                                                    \
    } while (0)

    // ---- prologue: stages 0..3 in flight; publish stage 0 ----
    ISSUE_AT(sb + 0 * STG, 0); CP_COMMIT();
    ISSUE_AT(sb + 1 * STG, 1); CP_COMMIT();
    ISSUE_AT(sb + 2 * STG, 2); CP_COMMIT();
    ISSUE_AT(sb + 3 * STG, 3); CP_COMMIT();
    CP_WAIT3();                // stage 0 landed (own chunks)
    __syncthreads();           // stage 0 visible to all
    LOADB(0, sb, 0);           // B[kt=0, ks=0] -> buf0

    uint32_t pbase = sb + 4 * STG;   // slot of (kt-1)%5 == (kt+4)%5
    uint32_t base  = sb;             // slot of kt
    uint32_t nbase = sb + STG;       // slot of kt+1
    const uint32_t send = sb + NST * STG;

#pragma unroll 1
    for (int kt = 0; kt < NKT; ++kt) {
        // ---- ks0 ----  (B in bt[0], loaded prev ks3 / prologue)
        LOADA(base, 0);
        LOADB(1, base, 1);
        MMAS(0);
        // ---- ks1 ----  mid-iteration sync point (60 MMAs still queued after)
        LOADA(base, 1);
        CP_WAIT2();            // stage kt+1 (own chunks) complete
        __syncthreads();       // publish stage kt+1; all warps past slot (kt-1)
        if (kt + 4 < NKT) ISSUE_AT(pbase, kt + 4);
        CP_COMMIT();
        LOADB(0, base, 2);
        MMAS(1);
        // ---- ks2 ----
        LOADA(base, 2);
        LOADB(1, base, 3);
        MMAS(0);
        // ---- ks3 ----
        LOADA(base, 3);
        if (kt + 1 < NKT) LOADB(0, nbase, 0);   // next-iter ks0 from stage kt+1
        MMAS(1);
        // rotate ring bases
        pbase = base;
        base = nbase;
        nbase += STG;
        if (nbase == send) nbase = sb;
    }

    // ---- epilogue ----
#pragma unroll
    for (int mt = 0; mt < 4; mt++) {
        int rloc0 = wm * 64 + mt * 16 + (lane >> 2);
#pragma unroll
        for (int half = 0; half < 2; half++) {
            int r = m0 + rloc0 + half * 8;
            if (r >= Me) continue;
            size_t orow = (size_t)(gbase + r) * (size_t)((MODE == 2) ? HH : II);
            float* Out = (MODE == 0) ? g_gate : (MODE == 1) ? g_up : g_dn;
            float wgt = (MODE == 2) ? g_roww[gbase + r] : 1.f;
#pragma unroll
            for (int nt = 0; nt < 5; nt++) {
                int col = n0 + wn * 40 + nt * 8 + (lane & 3) * 2;
                float v0 = acc[mt][nt][half * 2 + 0] + Bias[e * HH + col];
                float v1 = acc[mt][nt][half * 2 + 1] + Bias[e * HH + col + 1];
                if (MODE == 2) { v0 *= wgt; v1 *= wgt; }
                Out[orow + col]     = v0;
                Out[orow + col + 1] = v1;
            }
        }
    }
#undef ISSUE_AT
#undef LOADA
#undef LOADB
#undef MMAS
}

// ---------------- clipped SwiGLU -> fp16 h -------------------------------
__global__ void act_kernel() {
    size_t idx = ((size_t)blockIdx.x * 256 + threadIdx.x) * 4;
    float4 g = *(const float4*)&g_gate[idx];
    float4 u = *(const float4*)&g_up[idx];
    float gv[4] = {g.x, g.y, g.z, g.w};
    float uv[4] = {u.x, u.y, u.z, u.w};
    float r[4];
#pragma unroll
    for (int i = 0; i < 4; i++) {
        float gg = fminf(gv[i], LIMIT);
        float uu = fminf(fmaxf(uv[i], -LIMIT), LIMIT);
        float s = 1.f / (1.f + __expf(-ALPHA * gg));
        r[i] = (uu + 1.f) * (gg * s);
    }
    uint2 o;
    o.x = pack_h2(r[0], r[1]);
    o.y = pack_h2(r[2], r[3]);
    *(uint2*)((char*)g_h16 + idx * 2) = o;
}

// ---------------- per-token fixed-order combine -------------------------
__global__ void combine_kernel(float* __restrict__ y) {
    int t = blockIdx.x;
    const float* r0 = g_dn + (size_t)g_pos[t * 4 + 0] * HH;
    const float* r1 = g_dn + (size_t)g_pos[t * 4 + 1] * HH;
    const float* r2 = g_dn + (size_t)g_pos[t * 4 + 2] * HH;
    const float* r3 = g_dn + (size_t)g_pos[t * 4 + 3] * HH;
    float* yo = y + (size_t)t * HH;
    for (int c = threadIdx.x * 4; c < HH; c += 256 * 4) {
        float4 a = *(const float4*)(r0 + c);
        float4 b = *(const float4*)(r1 + c);
        float4 d = *(const float4*)(r2 + c);
        float4 f = *(const float4*)(r3 + c);
        *(float4*)(yo + c) = make_float4(a.x + b.x + d.x + f.x, a.y + b.y + d.y + f.y,
                                         a.z + b.z + d.z + f.z, a.w + b.w + d.w + f.w);
    }
}

// ---------------- launch ------------------------------------------------
extern "C" void kernel_launch(void* const* d_in, const int* in_sizes, int n_in,
                              void* d_out, int out_size) {
    const float* x  = (const float*)d_in[0];
    const float* rw = (const float*)d_in[1];
    const float* rb = (const float*)d_in[2];
    const float* w1 = (const float*)d_in[3];
    const float* b1 = (const float*)d_in[4];
    const float* w3 = (const float*)d_in[5];
    const float* b3 = (const float*)d_in[6];
    const float* w2 = (const float*)d_in[7];
    const float* b2 = (const float*)d_in[8];
    float* y = (float*)d_out;

    __half* x16p;  cudaGetSymbolAddress((void**)&x16p,  g_x16);
    __half* w1p;   cudaGetSymbolAddress((void**)&w1p,   g_w1h);
    __half* w3p;   cudaGetSymbolAddress((void**)&w3p,   g_w3h);
    __half* w2p;   cudaGetSymbolAddress((void**)&w2p,   g_w2h);

    cudaFuncSetAttribute(moe_gemm<0>, cudaFuncAttributeMaxDynamicSharedMemorySize, SMEM_BYTES);
    cudaFuncSetAttribute(moe_gemm<1>, cudaFuncAttributeMaxDynamicSharedMemorySize, SMEM_BYTES);
    cudaFuncSetAttribute(moe_gemm<2>, cudaFuncAttributeMaxDynamicSharedMemorySize, SMEM_BYTES);

    const size_t WSZ = (size_t)EE * II * HH;       // 132,710,400
    cvt16<<<(TT * HH) / 2048, 256>>>(x, x16p);     // 1440 blocks
    cvt16<<<WSZ / 2048, 256>>>(w1, w1p);           // 64800 blocks
    cvt16<<<WSZ / 2048, 256>>>(w3, w3p);
    cvt16<<<WSZ / 2048, 256>>>(w2, w2p);

    router_kernel<<<TT, 128>>>(x, rw, rb);
    group_kernel<<<1, 256>>>();

    dim3 ggrid(HH / BN, 8, EE);   // (18, 8, 16)
    moe_gemm<0><<<ggrid, 256, SMEM_BYTES>>>(w1p, b1);
    moe_gemm<1><<<ggrid, 256, SMEM_BYTES>>>(w3p, b3);

    act_kernel<<<(NROWS * II) / (256 * 4), 256>>>();

    moe_gemm<2><<<ggrid, 256, SMEM_BYTES>>>(w2p, b2);

    combine_kernel<<<TT, 256>>>(y);
}

// round 12
// speedup vs baseline: 2.2467x; 1.0690x over previous
#include <cuda_runtime.h>
#include <cuda_fp16.h>
#include <math.h>
#include <stdint.h>

#define TT 1024
#define HH 2880
#define II 2880
#define EE 16
#define KTOP 4
#define NROWS (TT * KTOP)
#define ALPHA 1.702f
#define LIMIT 7.0f

// fp16 GEMM tiling: BM=64, BN=160, BKH=64 halves; 2 CTAs/SM
#define BM 64
#define BN 160
#define BKH 64
#define NKT (HH / BKH)            // 45
#define A_ST (BM * 128)           // 8192 B per stage
#define B_ST (BN * 128)           // 20480 B per stage
#define STG (A_ST + B_ST)         // 28672
#define NST 4
#define SMEM_BYTES (NST * STG)    // 114688 (x2 CTAs = 229376 <= 228KB SM)

// ---------------- scratch -----------------------------------------------
__device__ float  g_gate[(size_t)NROWS * II];
__device__ float  g_up[(size_t)NROWS * II];
__device__ float  g_dn[(size_t)NROWS * HH];
__device__ __half g_h16[(size_t)NROWS * II];     // act output (GEMM3 A)
__device__ __half g_x16[(size_t)TT * HH];        // x in fp16
__device__ __half g_w1h[(size_t)EE * II * HH];
__device__ __half g_w3h[(size_t)EE * II * HH];
__device__ __half g_w2h[(size_t)EE * HH * II];
__device__ int    g_offs[EE + 1];
__device__ int    g_pos[NROWS];
__device__ int    g_rowtok[NROWS];
__device__ float  g_roww[NROWS];
__device__ int    g_tidx[NROWS];
__device__ float  g_tw[NROWS];

// ---------------- helpers -----------------------------------------------
__device__ __forceinline__ unsigned pack_h2(float lo, float hi) {
    __half2 h = __floats2half2_rn(lo, hi);
    return *reinterpret_cast<unsigned*>(&h);
}
__device__ __forceinline__ uint32_t smem_u32(const void* p) {
    uint32_t a;
    asm("{ .reg .u64 t; cvta.to.shared.u64 t, %1; cvt.u32.u64 %0, t; }" : "=r"(a) : "l"(p));
    return a;
}
__device__ __forceinline__ uint32_t SWZ(uint32_t off) {
    return off ^ ((off >> 3) & 0x70u);
}
#define CP_ASYNC16(dst, src)                                                \
    asm volatile("cp.async.cg.shared.global [%0], [%1], 16;" ::"r"(dst), "l"(src) : "memory")
#define CP_COMMIT() asm volatile("cp.async.commit_group;" ::: "memory")
#define CP_WAIT2()  asm volatile("cp.async.wait_group 2;" ::: "memory")

__device__ __forceinline__ void ldsm4(unsigned* r, uint32_t addr) {
    asm volatile("ldmatrix.sync.aligned.m8n8.x4.shared.b16 {%0,%1,%2,%3}, [%4];"
                 : "=r"(r[0]), "=r"(r[1]), "=r"(r[2]), "=r"(r[3]) : "r"(addr));
}
__device__ __forceinline__ void ldsm2(unsigned* r, uint32_t addr) {
    asm volatile("ldmatrix.sync.aligned.m8n8.x2.shared.b16 {%0,%1}, [%2];"
                 : "=r"(r[0]), "=r"(r[1]) : "r"(addr));
}
__device__ __forceinline__ void mma16(float* d, const unsigned* a, const unsigned* b) {
    asm volatile(
        "mma.sync.aligned.m16n8k16.row.col.f32.f16.f16.f32 "
        "{%0,%1,%2,%3}, {%4,%5,%6,%7}, {%8,%9}, {%0,%1,%2,%3};"
        : "+f"(d[0]), "+f"(d[1]), "+f"(d[2]), "+f"(d[3])
        : "r"(a[0]), "r"(a[1]), "r"(a[2]), "r"(a[3]), "r"(b[0]), "r"(b[1]));
}

// ---------------- fp32 -> fp16 streaming convert -------------------------
__global__ void cvt16(const float* __restrict__ s, __half* __restrict__ d) {
    size_t i = ((size_t)blockIdx.x * 256 + threadIdx.x) * 8;
    float4 a = *(const float4*)(s + i);
    float4 b = *(const float4*)(s + i + 4);
    uint4 o;
    o.x = pack_h2(a.x, a.y);
    o.y = pack_h2(a.z, a.w);
    o.z = pack_h2(b.x, b.y);
    o.w = pack_h2(b.z, b.w);
    *(uint4*)((char*)d + i * 2) = o;
}

// ---------------- router ------------------------------------------------
__global__ void router_kernel(const float* __restrict__ x,
                              const float* __restrict__ rw,
                              const float* __restrict__ rb) {
    int t = blockIdx.x;
    int tid = threadIdx.x;
    float acc[EE];
#pragma unroll
    for (int e = 0; e < EE; e++) acc[e] = 0.f;
    const float* xr = x + (size_t)t * HH;
    for (int h = tid; h < HH; h += 128) {
        float xv = xr[h];
#pragma unroll
        for (int e = 0; e < EE; e++) acc[e] = fmaf(xv, rw[e * HH + h], acc[e]);
    }
#pragma unroll
    for (int e = 0; e < EE; e++) {
#pragma unroll
        for (int o = 16; o > 0; o >>= 1) acc[e] += __shfl_xor_sync(0xffffffffu, acc[e], o);
    }
    __shared__ float sl[4][EE];
    int w = tid >> 5;
    if ((tid & 31) == 0) {
#pragma unroll
        for (int e = 0; e < EE; e++) sl[w][e] = acc[e];
    }
    __syncthreads();
    if (tid == 0) {
        float lg[EE];
        float mx = -1e30f;
#pragma unroll
        for (int e = 0; e < EE; e++) {
            lg[e] = sl[0][e] + sl[1][e] + sl[2][e] + sl[3][e] + rb[e];
            mx = fmaxf(mx, lg[e]);
        }
        float p[EE];
#pragma unroll
        for (int e = 0; e < EE; e++) p[e] = __expf(lg[e] - mx);
        bool used[EE];
#pragma unroll
        for (int e = 0; e < EE; e++) used[e] = false;
        int sel[KTOP]; float pv[KTOP]; float psum = 0.f;
        for (int k = 0; k < KTOP; k++) {
            int best = 0; float bv = -1.f;
            for (int e = 0; e < EE; e++)
                if (!used[e] && p[e] > bv) { bv = p[e]; best = e; }
            used[best] = true; sel[k] = best; pv[k] = bv; psum += bv;
        }
        float inv = 1.f / psum;
        for (int k = 0; k < KTOP; k++) {
            g_tidx[t * 4 + k] = sel[k];
            g_tw[t * 4 + k]   = pv[k] * inv;
        }
    }
}

// ---------------- deterministic grouping --------------------------------
__global__ void group_kernel() {
    __shared__ unsigned char eid[NROWS];
    __shared__ int base[EE];
    int tid = threadIdx.x;
    for (int i = tid; i < NROWS; i += blockDim.x) eid[i] = (unsigned char)g_tidx[i];
    __syncthreads();
    if (tid == 0) {
        int cnt[EE];
        for (int e = 0; e < EE; e++) cnt[e] = 0;
        for (int i = 0; i < NROWS; i++) cnt[eid[i]]++;
        int s = 0;
        for (int e = 0; e < EE; e++) { base[e] = s; g_offs[e] = s; s += cnt[e]; }
        g_offs[EE] = s;
    }
    __syncthreads();
    if (tid < EE) {
        int cur = base[tid];
        for (int i = 0; i < NROWS; i++) {
            if (eid[i] == (unsigned char)tid) {
                g_pos[i] = cur;
                g_rowtok[cur] = i >> 2;
                g_roww[cur] = g_tw[i];
                cur++;
            }
        }
    }
}

// ---------------- grouped GEMM: fp16, BM=64, 2 CTAs/SM -------------------
template<int MODE>
__global__ __launch_bounds__(256, 2)
void moe_gemm(const __half* __restrict__ Wh, const float* __restrict__ Bias) {
    const int e = blockIdx.z;
    const int gbase = g_offs[e];
    const int Me = g_offs[e + 1] - gbase;
    const int m0 = blockIdx.y * BM;
    if (m0 >= Me) return;
    const int n0 = blockIdx.x * BN;

    extern __shared__ char smraw[];
    const uint32_t sb = smem_u32(smraw);
    const int tid = threadIdx.x;
    const int lane = tid & 31;
    const int warp = tid >> 5;
    const int wm = warp >> 2;                  // 0..1 (M 32 each)
    const int wn = warp & 3;                   // 0..3 (N 40 each)

    float acc[2][5][4];
#pragma unroll
    for (int i = 0; i < 2; i++)
#pragma unroll
        for (int j = 0; j < 5; j++)
#pragma unroll
            for (int q = 0; q < 4; q++) acc[i][j][q] = 0.f;

    // ---- A cp.async chunks: 512 total, 2 per thread ----
    const __half* gA[2]; uint32_t sA[2];
#pragma unroll
    for (int j = 0; j < 2; j++) {
        int c = tid + j * 256;
        int row = c >> 3, kc = c & 7;
        int r = m0 + row;
        if (r >= Me) r = 0;                    // clamp: garbage-safe (row unstored)
        const __half* rowp;
        if (MODE == 2) rowp = g_h16 + (size_t)(gbase + r) * II;
        else           rowp = g_x16 + (size_t)g_rowtok[gbase + r] * HH;
        gA[j] = rowp + kc * 8;
        sA[j] = SWZ((uint32_t)(row * 128 + kc * 16));
    }
    // ---- B cp.async chunks: 1280 total, 5 per thread ----
    const __half* gB[5]; uint32_t sB[5];
#pragma unroll
    for (int j = 0; j < 5; j++) {
        int c = tid + j * 256;
        int row = c >> 3, kc = c & 7;
        gB[j] = Wh + (size_t)e * HH * II + (size_t)(n0 + row) * HH + kc * 8;
        sB[j] = A_ST + SWZ((uint32_t)(row * 128 + kc * 16));
    }

#define ISSUE(st)                                                            \
    do {                                                                     \
        uint32_t _b = sb + ((st) & 3) * STG;                                 \
        int _k = (st) * BKH;                                                 \
        CP_ASYNC16(_b + sA[0], gA[0] + _k);                                  \
        CP_ASYNC16(_b + sA[1], gA[1] + _k);                                  \
        CP_ASYNC16(_b + sB[0], gB[0] + _k);                                  \
        CP_ASYNC16(_b + sB[1], gB[1] + _k);                                  \
        CP_ASYNC16(_b + sB[2], gB[2] + _k);                                  \
        CP_ASYNC16(_b + sB[3], gB[3] + _k);                                  \
        CP_ASYNC16(_b + sB[4], gB[4] + _k);                                  \
    } while (0)

    // ---- ldsm raw offsets + per-lane swizzle masks ----
    const uint32_t axorm = (uint32_t)((lane & 7) << 4);
    const int lane15 = lane & 15;
    const uint32_t b2xor = (uint32_t)((lane15 & 7) << 4);
    uint32_t araw[2];
#pragma unroll
    for (int mt = 0; mt < 2; mt++) {
        int R = wm * 32 + mt * 16 + (lane & 7) + ((lane >> 3) & 1) * 8;
        araw[mt] = (uint32_t)(R * 128 + ((lane >> 4) & 1) * 16);
    }
    const uint32_t braw0 = (uint32_t)(A_ST + (wn * 40 + (lane & 7) + ((lane >> 4) & 1) * 8) * 128 +
                                      ((lane >> 3) & 1) * 16);
    const uint32_t braw1 = braw0 + 16 * 128;
    const uint32_t braw2 = (uint32_t)(A_ST + (wn * 40 + 32 + (lane15 & 7)) * 128 +
                                      ((lane15 >> 3) & 1) * 16);

    unsigned af[2][4], bt0[2][4], bt1[2][4], bt2[2][2];

#define LOADA(bbase, ks)                                                     \
    do {                                                                     \
        uint32_t _o = (uint32_t)((ks) * 32);                                 \
        ldsm4(af[0], (bbase) + ((araw[0] + _o) ^ axorm));                    \
        ldsm4(af[1], (bbase) + ((araw[1] + _o) ^ axorm));                    \
    } while (0)
#define LOADB(buf, bbase, ks)                                                \
    do {                                                                     \
        uint32_t _o = (uint32_t)((ks) * 32);                                 \
        ldsm4(bt0[buf], (bbase) + ((braw0 + _o) ^ axorm));                   \
        ldsm4(bt1[buf], (bbase) + ((braw1 + _o) ^ axorm));                   \
        ldsm2(bt2[buf], (bbase) + ((braw2 + _o) ^ b2xor));                   \
    } while (0)
#define MMAS(buf)                                                            \
    do {                                                                     \
        _Pragma("unroll")                                                    \
        for (int mt = 0; mt < 2; mt++) {                                     \
            mma16(acc[mt][0], af[mt], &bt0[buf][0]);                         \
            mma16(acc[mt][1], af[mt], &bt0[buf][2]);                         \
            mma16(acc[mt][2], af[mt], &bt1[buf][0]);                         \
            mma16(acc[mt][3], af[mt], &bt1[buf][2]);                         \
            mma16(acc[mt][4], af[mt], bt2[buf]);                             \
        }                                                                    \
    } while (0)

    // ---- prologue: stages 0..2 in flight ----
    ISSUE(0); CP_COMMIT();
    ISSUE(1); CP_COMMIT();
    ISSUE(2); CP_COMMIT();

#pragma unroll 1
    for (int kt = 0; kt < NKT; ++kt) {
        CP_WAIT2();            // stage kt (own chunks) complete
        __syncthreads();       // visible to all; slot (kt-1)&3 free
        if (kt + 3 < NKT) ISSUE(kt + 3);
        CP_COMMIT();

        uint32_t base = sb + (kt & 3) * STG;
        LOADB(0, base, 0);
        // ks0
        LOADA(base, 0); LOADB(1, base, 1); MMAS(0);
        // ks1
        LOADA(base, 1); LOADB(0, base, 2); MMAS(1);
        // ks2
        LOADA(base, 2); LOADB(1, base, 3); MMAS(0);
        // ks3
        LOADA(base, 3); MMAS(1);
    }

    // ---- epilogue ----
#pragma unroll
    for (int mt = 0; mt < 2; mt++) {
        int rloc0 = wm * 32 + mt * 16 + (lane >> 2);
#pragma unroll
        for (int half = 0; half < 2; half++) {
            int r = m0 + rloc0 + half * 8;
            if (r >= Me) continue;
            size_t orow = (size_t)(gbase + r) * (size_t)((MODE == 2) ? HH : II);
            float* Out = (MODE == 0) ? g_gate : (MODE == 1) ? g_up : g_dn;
            float wgt = (MODE == 2) ? g_roww[gbase + r] : 1.f;
#pragma unroll
            for (int nt = 0; nt < 5; nt++) {
                int col = n0 + wn * 40 + nt * 8 + (lane & 3) * 2;
                float v0 = acc[mt][nt][half * 2 + 0] + Bias[e * HH + col];
                float v1 = acc[mt][nt][half * 2 + 1] + Bias[e * HH + col + 1];
                if (MODE == 2) { v0 *= wgt; v1 *= wgt; }
                Out[orow + col]     = v0;
                Out[orow + col + 1] = v1;
            }
        }
    }
#undef ISSUE
#undef LOADA
#undef LOADB
#undef MMAS
}

// ---------------- clipped SwiGLU -> fp16 h -------------------------------
__global__ void act_kernel() {
    size_t idx = ((size_t)blockIdx.x * 256 + threadIdx.x) * 4;
    float4 g = *(const float4*)&g_gate[idx];
    float4 u = *(const float4*)&g_up[idx];
    float gv[4] = {g.x, g.y, g.z, g.w};
    float uv[4] = {u.x, u.y, u.z, u.w};
    float r[4];
#pragma unroll
    for (int i = 0; i < 4; i++) {
        float gg = fminf(gv[i], LIMIT);
        float uu = fminf(fmaxf(uv[i], -LIMIT), LIMIT);
        float s = 1.f / (1.f + __expf(-ALPHA * gg));
        r[i] = (uu + 1.f) * (gg * s);
    }
    uint2 o;
    o.x = pack_h2(r[0], r[1]);
    o.y = pack_h2(r[2], r[3]);
    *(uint2*)((char*)g_h16 + idx * 2) = o;
}

// ---------------- per-token fixed-order combine -------------------------
__global__ void combine_kernel(float* __restrict__ y) {
    int t = blockIdx.x;
    const float* r0 = g_dn + (size_t)g_pos[t * 4 + 0] * HH;
    const float* r1 = g_dn + (size_t)g_pos[t * 4 + 1] * HH;
    const float* r2 = g_dn + (size_t)g_pos[t * 4 + 2] * HH;
    const float* r3 = g_dn + (size_t)g_pos[t * 4 + 3] * HH;
    float* yo = y + (size_t)t * HH;
    for (int c = threadIdx.x * 4; c < HH; c += 256 * 4) {
        float4 a = *(const float4*)(r0 + c);
        float4 b = *(const float4*)(r1 + c);
        float4 d = *(const float4*)(r2 + c);
        float4 f = *(const float4*)(r3 + c);
        *(float4*)(yo + c) = make_float4(a.x + b.x + d.x + f.x, a.y + b.y + d.y + f.y,
                                         a.z + b.z + d.z + f.z, a.w + b.w + d.w + f.w);
    }
}

// ---------------- launch ------------------------------------------------
extern "C" void kernel_launch(void* const* d_in, const int* in_sizes, int n_in,
                              void* d_out, int out_size) {
    const float* x  = (const float*)d_in[0];
    const float* rw = (const float*)d_in[1];
    const float* rb = (const float*)d_in[2];
    const float* w1 = (const float*)d_in[3];
    const float* b1 = (const float*)d_in[4];
    const float* w3 = (const float*)d_in[5];
    const float* b3 = (const float*)d_in[6];
    const float* w2 = (const float*)d_in[7];
    const float* b2 = (const float*)d_in[8];
    float* y = (float*)d_out;

    __half* x16p;  cudaGetSymbolAddress((void**)&x16p,  g_x16);
    __half* w1p;   cudaGetSymbolAddress((void**)&w1p,   g_w1h);
    __half* w3p;   cudaGetSymbolAddress((void**)&w3p,   g_w3h);
    __half* w2p;   cudaGetSymbolAddress((void**)&w2p,   g_w2h);

    cudaFuncSetAttribute(moe_gemm<0>, cudaFuncAttributeMaxDynamicSharedMemorySize, SMEM_BYTES);
    cudaFuncSetAttribute(moe_gemm<1>, cudaFuncAttributeMaxDynamicSharedMemorySize, SMEM_BYTES);
    cudaFuncSetAttribute(moe_gemm<2>, cudaFuncAttributeMaxDynamicSharedMemorySize, SMEM_BYTES);

    const size_t WSZ = (size_t)EE * II * HH;       // 132,710,400
    dim3 ggrid(HH / BN, 16, EE);   // (18, 16, 16) for BM=64

    // Order chosen so moe_gemm<0> is the 6th launch (ncu -s 5 -c 1 window).
    cvt16<<<(TT * HH) / 2048, 256>>>(x, x16p);     // 1
    cvt16<<<WSZ / 2048, 256>>>(w1, w1p);           // 2
    router_kernel<<<TT, 128>>>(x, rw, rb);         // 3
    group_kernel<<<1, 256>>>();                    // 4
    cvt16<<<WSZ / 2048, 256>>>(w3, w3p);           // 5
    moe_gemm<0><<<ggrid, 256, SMEM_BYTES>>>(w1p, b1);   // 6 <- profiled
    moe_gemm<1><<<ggrid, 256, SMEM_BYTES>>>(w3p, b3);   // 7
    act_kernel<<<(NROWS * II) / (256 * 4), 256>>>();    // 8
    cvt16<<<WSZ / 2048, 256>>>(w2, w2p);                // 9
    moe_gemm<2><<<ggrid, 256, SMEM_BYTES>>>(w2p, b2);   // 10
    combine_kernel<<<TT, 256>>>(y);                     // 11
}

// round 15
// speedup vs baseline: 2.8208x; 1.2555x over previous
#include <cuda_runtime.h>
#include <cuda_fp16.h>
#include <math.h>
#include <stdint.h>

#define TT 1024
#define HH 2880
#define II 2880
#define EE 16
#define KTOP 4
#define NROWS (TT * KTOP)
#define ALPHA 1.702f
#define LIMIT 7.0f

// fp16 GEMM tiling: BM=64, BN=160, BKH=64 halves; 2 CTAs/SM
#define BM 64
#define BN 160
#define BKH 64
#define NKT (HH / BKH)            // 45
#define A_ST (BM * 128)           // 8192 B per stage
#define B_ST (BN * 128)           // 20480 B per stage
#define STG (A_ST + B_ST)         // 28672
#define NST 4
#define SMEM_BYTES (NST * STG)    // 114688 (x2 CTAs = 229376 <= 228KB SM)

// ---------------- scratch -----------------------------------------------
__device__ float  g_gate[(size_t)NROWS * II];
__device__ float  g_up[(size_t)NROWS * II];
__device__ float  g_dn[(size_t)NROWS * HH];
__device__ __half g_h16[(size_t)NROWS * II];     // act output (GEMM3 A)
__device__ __half g_x16[(size_t)TT * HH];        // x in fp16
__device__ __half g_w1h[(size_t)EE * II * HH];
__device__ __half g_w3h[(size_t)EE * II * HH];
__device__ __half g_w2h[(size_t)EE * HH * II];
__device__ int    g_offs[EE + 1];
__device__ int    g_pos[NROWS];
__device__ int    g_rowtok[NROWS];
__device__ float  g_roww[NROWS];
__device__ int    g_tidx[NROWS];
__device__ float  g_tw[NROWS];

// ---------------- helpers -----------------------------------------------
__device__ __forceinline__ unsigned pack_h2(float lo, float hi) {
    __half2 h = __floats2half2_rn(lo, hi);
    return *reinterpret_cast<unsigned*>(&h);
}
__device__ __forceinline__ uint32_t smem_u32(const void* p) {
    uint32_t a;
    asm("{ .reg .u64 t; cvta.to.shared.u64 t, %1; cvt.u32.u64 %0, t; }" : "=r"(a) : "l"(p));
    return a;
}
__device__ __forceinline__ uint32_t SWZ(uint32_t off) {
    return off ^ ((off >> 3) & 0x70u);
}
#define CP_ASYNC16(dst, src)                                                \
    asm volatile("cp.async.cg.shared.global [%0], [%1], 16;" ::"r"(dst), "l"(src) : "memory")
#define CP_COMMIT() asm volatile("cp.async.commit_group;" ::: "memory")
#define CP_WAIT2()  asm volatile("cp.async.wait_group 2;" ::: "memory")

__device__ __forceinline__ void ldsm4(unsigned* r, uint32_t addr) {
    asm volatile("ldmatrix.sync.aligned.m8n8.x4.shared.b16 {%0,%1,%2,%3}, [%4];"
                 : "=r"(r[0]), "=r"(r[1]), "=r"(r[2]), "=r"(r[3]) : "r"(addr));
}
__device__ __forceinline__ void ldsm2(unsigned* r, uint32_t addr) {
    asm volatile("ldmatrix.sync.aligned.m8n8.x2.shared.b16 {%0,%1}, [%2];"
                 : "=r"(r[0]), "=r"(r[1]) : "r"(addr));
}
__device__ __forceinline__ void mma16(float* d, const unsigned* a, const unsigned* b) {
    asm volatile(
        "mma.sync.aligned.m16n8k16.row.col.f32.f16.f16.f32 "
        "{%0,%1,%2,%3}, {%4,%5,%6,%7}, {%8,%9}, {%0,%1,%2,%3};"
        : "+f"(d[0]), "+f"(d[1]), "+f"(d[2]), "+f"(d[3])
        : "r"(a[0]), "r"(a[1]), "r"(a[2]), "r"(a[3]), "r"(b[0]), "r"(b[1]));
}

// ---------------- fp32 -> fp16 streaming convert -------------------------
__global__ void cvt16(const float* __restrict__ s, __half* __restrict__ d) {
    size_t i = ((size_t)blockIdx.x * 256 + threadIdx.x) * 8;
    float4 a = *(const float4*)(s + i);
    float4 b = *(const float4*)(s + i + 4);
    uint4 o;
    o.x = pack_h2(a.x, a.y);
    o.y = pack_h2(a.z, a.w);
    o.z = pack_h2(b.x, b.y);
    o.w = pack_h2(b.z, b.w);
    *(uint4*)((char*)d + i * 2) = o;
}

// ---------------- router ------------------------------------------------
__global__ void router_kernel(const float* __restrict__ x,
                              const float* __restrict__ rw,
                              const float* __restrict__ rb) {
    int t = blockIdx.x;
    int tid = threadIdx.x;
    float acc[EE];
#pragma unroll
    for (int e = 0; e < EE; e++) acc[e] = 0.f;
    const float* xr = x + (size_t)t * HH;
    for (int h = tid; h < HH; h += 128) {
        float xv = xr[h];
#pragma unroll
        for (int e = 0; e < EE; e++) acc[e] = fmaf(xv, rw[e * HH + h], acc[e]);
    }
#pragma unroll
    for (int e = 0; e < EE; e++) {
#pragma unroll
        for (int o = 16; o > 0; o >>= 1) acc[e] += __shfl_xor_sync(0xffffffffu, acc[e], o);
    }
    __shared__ float sl[4][EE];
    int w = tid >> 5;
    if ((tid & 31) == 0) {
#pragma unroll
        for (int e = 0; e < EE; e++) sl[w][e] = acc[e];
    }
    __syncthreads();
    if (tid == 0) {
        float lg[EE];
        float mx = -1e30f;
#pragma unroll
        for (int e = 0; e < EE; e++) {
            lg[e] = sl[0][e] + sl[1][e] + sl[2][e] + sl[3][e] + rb[e];
            mx = fmaxf(mx, lg[e]);
        }
        float p[EE];
#pragma unroll
        for (int e = 0; e < EE; e++) p[e] = __expf(lg[e] - mx);
        bool used[EE];
#pragma unroll
        for (int e = 0; e < EE; e++) used[e] = false;
        int sel[KTOP]; float pv[KTOP]; float psum = 0.f;
        for (int k = 0; k < KTOP; k++) {
            int best = 0; float bv = -1.f;
            for (int e = 0; e < EE; e++)
                if (!used[e] && p[e] > bv) { bv = p[e]; best = e; }
            used[best] = true; sel[k] = best; pv[k] = bv; psum += bv;
        }
        float inv = 1.f / psum;
        for (int k = 0; k < KTOP; k++) {
            g_tidx[t * 4 + k] = sel[k];
            g_tw[t * 4 + k]   = pv[k] * inv;
        }
    }
}

// ---------------- deterministic grouping (parallel, stable) --------------
// 16 warps, warp e handles expert e. Placement order == original index
// order (stable), identical to the old serial version.
__global__ void group_kernel() {
    __shared__ unsigned char eid[NROWS];
    __shared__ int cnt[EE];
    const int tid = threadIdx.x;
    const int warp = tid >> 5, lane = tid & 31;
    for (int i = tid; i < NROWS; i += 512)
        eid[i] = (unsigned char)g_tidx[i];
    __syncthreads();
    // count per expert
    {
        int c = 0;
        for (int i = lane; i < NROWS; i += 32) c += (eid[i] == (unsigned char)warp);
#pragma unroll
        for (int o = 16; o > 0; o >>= 1) c += __shfl_xor_sync(0xffffffffu, c, o);
        if (lane == 0) cnt[warp] = c;
    }
    __syncthreads();
    if (tid == 0) {
        int s = 0;
        for (int e = 0; e < EE; e++) { g_offs[e] = s; s += cnt[e]; }
        g_offs[EE] = s;
    }
    __syncthreads();
    // stable placement via ballot rank
    {
        int base = g_offs[warp];
        const unsigned lt = (lane == 0) ? 0u : (0xffffffffu >> (32 - lane));
        for (int i0 = 0; i0 < NROWS; i0 += 32) {
            int i = i0 + lane;
            bool m = (eid[i] == (unsigned char)warp);
            unsigned mask = __ballot_sync(0xffffffffu, m);
            if (m) {
                int pos = base + __popc(mask & lt);
                g_pos[i] = pos;
                g_rowtok[pos] = i >> 2;
                g_roww[pos] = g_tw[i];
            }
            base += __popc(mask);
        }
    }
}

// ---------------- grouped GEMM: fp16, BM=64, 2 CTAs/SM -------------------
template<int MODE>
__global__ __launch_bounds__(256, 2)
void moe_gemm(const __half* __restrict__ Wh, const float* __restrict__ Bias) {
    const int e = blockIdx.z;
    const int gbase = g_offs[e];
    const int Me = g_offs[e + 1] - gbase;
    const int m0 = blockIdx.y * BM;
    if (m0 >= Me) return;
    const int n0 = blockIdx.x * BN;

    extern __shared__ char smraw[];
    const uint32_t sb = smem_u32(smraw);
    const int tid = threadIdx.x;
    const int lane = tid & 31;
    const int warp = tid >> 5;
    const int wm = warp >> 2;                  // 0..1 (M 32 each)
    const int wn = warp & 3;                   // 0..3 (N 40 each)

    float acc[2][5][4];
#pragma unroll
    for (int i = 0; i < 2; i++)
#pragma unroll
        for (int j = 0; j < 5; j++)
#pragma unroll
            for (int q = 0; q < 4; q++) acc[i][j][q] = 0.f;

    // ---- A cp.async chunks: 512 total, 2 per thread ----
    const __half* gA[2]; uint32_t sA[2];
#pragma unroll
    for (int j = 0; j < 2; j++) {
        int c = tid + j * 256;
        int row = c >> 3, kc = c & 7;
        int r = m0 + row;
        if (r >= Me) r = 0;                    // clamp: garbage-safe (row unstored)
        const __half* rowp;
        if (MODE == 2) rowp = g_h16 + (size_t)(gbase + r) * II;
        else           rowp = g_x16 + (size_t)g_rowtok[gbase + r] * HH;
        gA[j] = rowp + kc * 8;
        sA[j] = SWZ((uint32_t)(row * 128 + kc * 16));
    }
    // ---- B cp.async chunks: 1280 total, 5 per thread ----
    const __half* gB[5]; uint32_t sB[5];
#pragma unroll
    for (int j = 0; j < 5; j++) {
        int c = tid + j * 256;
        int row = c >> 3, kc = c & 7;
        gB[j] = Wh + (size_t)e * HH * II + (size_t)(n0 + row) * HH + kc * 8;
        sB[j] = A_ST + SWZ((uint32_t)(row * 128 + kc * 16));
    }

#define ISSUE(st)                                                            \
    do {                                                                     \
        uint32_t _b = sb + ((st) & 3) * STG;                                 \
        int _k = (st) * BKH;                                                 \
        CP_ASYNC16(_b + sA[0], gA[0] + _k);                                  \
        CP_ASYNC16(_b + sA[1], gA[1] + _k);                                  \
        CP_ASYNC16(_b + sB[0], gB[0] + _k);                                  \
        CP_ASYNC16(_b + sB[1], gB[1] + _k);                                  \
        CP_ASYNC16(_b + sB[2], gB[2] + _k);                                  \
        CP_ASYNC16(_b + sB[3], gB[3] + _k);                                  \
        CP_ASYNC16(_b + sB[4], gB[4] + _k);                                  \
    } while (0)

    // ---- ldsm raw offsets + per-lane swizzle masks ----
    const uint32_t axorm = (uint32_t)((lane & 7) << 4);
    const int lane15 = lane & 15;
    const uint32_t b2xor = (uint32_t)((lane15 & 7) << 4);
    uint32_t araw[2];
#pragma unroll
    for (int mt = 0; mt < 2; mt++) {
        int R = wm * 32 + mt * 16 + (lane & 7) + ((lane >> 3) & 1) * 8;
        araw[mt] = (uint32_t)(R * 128 + ((lane >> 4) & 1) * 16);
    }
    const uint32_t braw0 = (uint32_t)(A_ST + (wn * 40 + (lane & 7) + ((lane >> 4) & 1) * 8) * 128 +
                                      ((lane >> 3) & 1) * 16);
    const uint32_t braw1 = braw0 + 16 * 128;
    const uint32_t braw2 = (uint32_t)(A_ST + (wn * 40 + 32 + (lane15 & 7)) * 128 +
                                      ((lane15 >> 3) & 1) * 16);

    unsigned af[2][4], bt0[2][4], bt1[2][4], bt2[2][2];

#define LOADA(bbase, ks)                                                     \
    do {                                                                     \
        uint32_t _o = (uint32_t)((ks) * 32);                                 \
        ldsm4(af[0], (bbase) + ((araw[0] + _o) ^ axorm));                    \
        ldsm4(af[1], (bbase) + ((araw[1] + _o) ^ axorm));                    \
    } while (0)
#define LOADB(buf, bbase, ks)                                                \
    do {                                                                     \
        uint32_t _o = (uint32_t)((ks) * 32);                                 \
        ldsm4(bt0[buf], (bbase) + ((braw0 + _o) ^ axorm));                   \
        ldsm4(bt1[buf], (bbase) + ((braw1 + _o) ^ axorm));                   \
        ldsm2(bt2[buf], (bbase) + ((braw2 + _o) ^ b2xor));                   \
    } while (0)
#define MMAS(buf)                                                            \
    do {                                                                     \
        _Pragma("unroll")                                                    \
        for (int mt = 0; mt < 2; mt++) {                                     \
            mma16(acc[mt][0], af[mt], &bt0[buf][0]);                         \
            mma16(acc[mt][1], af[mt], &bt0[buf][2]);                         \
            mma16(acc[mt][2], af[mt], &bt1[buf][0]);                         \
            mma16(acc[mt][3], af[mt], &bt1[buf][2]);                         \
            mma16(acc[mt][4], af[mt], bt2[buf]);                             \
        }                                                                    \
    } while (0)

    // ---- prologue: stages 0..2 in flight ----
    ISSUE(0); CP_COMMIT();
    ISSUE(1); CP_COMMIT();
    ISSUE(2); CP_COMMIT();

#pragma unroll 1
    for (int kt = 0; kt < NKT; ++kt) {
        CP_WAIT2();            // stage kt (own chunks) complete
        __syncthreads();       // visible to all; slot (kt-1)&3 free
        if (kt + 3 < NKT) ISSUE(kt + 3);
        CP_COMMIT();

        uint32_t base = sb + (kt & 3) * STG;
        LOADB(0, base, 0);
        // ks0
        LOADA(base, 0); LOADB(1, base, 1); MMAS(0);
        // ks1
        LOADA(base, 1); LOADB(0, base, 2); MMAS(1);
        // ks2
        LOADA(base, 2); LOADB(1, base, 3); MMAS(0);
        // ks3
        LOADA(base, 3); MMAS(1);
    }

    // ---- epilogue ----
#pragma unroll
    for (int mt = 0; mt < 2; mt++) {
        int rloc0 = wm * 32 + mt * 16 + (lane >> 2);
#pragma unroll
        for (int half = 0; half < 2; half++) {
            int r = m0 + rloc0 + half * 8;
            if (r >= Me) continue;
            size_t orow = (size_t)(gbase + r) * (size_t)((MODE == 2) ? HH : II);
            float* Out = (MODE == 0) ? g_gate : (MODE == 1) ? g_up : g_dn;
            float wgt = (MODE == 2) ? g_roww[gbase + r] : 1.f;
#pragma unroll
            for (int nt = 0; nt < 5; nt++) {
                int col = n0 + wn * 40 + nt * 8 + (lane & 3) * 2;
                float v0 = acc[mt][nt][half * 2 + 0] + Bias[e * HH + col];
                float v1 = acc[mt][nt][half * 2 + 1] + Bias[e * HH + col + 1];
                if (MODE == 2) { v0 *= wgt; v1 *= wgt; }
                Out[orow + col]     = v0;
                Out[orow + col + 1] = v1;
            }
        }
    }
#undef ISSUE
#undef LOADA
#undef LOADB
#undef MMAS
}

// ---------------- clipped SwiGLU -> fp16 h -------------------------------
__global__ void act_kernel() {
    size_t idx = ((size_t)blockIdx.x * 256 + threadIdx.x) * 4;
    float4 g = *(const float4*)&g_gate[idx];
    float4 u = *(const float4*)&g_up[idx];
    float gv[4] = {g.x, g.y, g.z, g.w};
    float uv[4] = {u.x, u.y, u.z, u.w};
    float r[4];
#pragma unroll
    for (int i = 0; i < 4; i++) {
        float gg = fminf(gv[i], LIMIT);
        float uu = fminf(fmaxf(uv[i], -LIMIT), LIMIT);
        float s = 1.f / (1.f + __expf(-ALPHA * gg));
        r[i] = (uu + 1.f) * (gg * s);
    }
    uint2 o;
    o.x = pack_h2(r[0], r[1]);
    o.y = pack_h2(r[2], r[3]);
    *(uint2*)((char*)g_h16 + idx * 2) = o;
}

// ---------------- per-token fixed-order combine -------------------------
__global__ void combine_kernel(float* __restrict__ y) {
    int t = blockIdx.x;
    const float* r0 = g_dn + (size_t)g_pos[t * 4 + 0] * HH;
    const float* r1 = g_dn + (size_t)g_pos[t * 4 + 1] * HH;
    const float* r2 = g_dn + (size_t)g_pos[t * 4 + 2] * HH;
    const float* r3 = g_dn + (size_t)g_pos[t * 4 + 3] * HH;
    float* yo = y + (size_t)t * HH;
    for (int c = threadIdx.x * 4; c < HH; c += 256 * 4) {
        float4 a = *(const float4*)(r0 + c);
        float4 b = *(const float4*)(r1 + c);
        float4 d = *(const float4*)(r2 + c);
        float4 f = *(const float4*)(r3 + c);
        *(float4*)(yo + c) = make_float4(a.x + b.x + d.x + f.x, a.y + b.y + d.y + f.y,
                                         a.z + b.z + d.z + f.z, a.w + b.w + d.w + f.w);
    }
}

// ---------------- launch ------------------------------------------------
extern "C" void kernel_launch(void* const* d_in, const int* in_sizes, int n_in,
                              void* d_out, int out_size) {
    const float* x  = (const float*)d_in[0];
    const float* rw = (const float*)d_in[1];
    const float* rb = (const float*)d_in[2];
    const float* w1 = (const float*)d_in[3];
    const float* b1 = (const float*)d_in[4];
    const float* w3 = (const float*)d_in[5];
    const float* b3 = (const float*)d_in[6];
    const float* w2 = (const float*)d_in[7];
    const float* b2 = (const float*)d_in[8];
    float* y = (float*)d_out;

    __half* x16p;  cudaGetSymbolAddress((void**)&x16p,  g_x16);
    __half* w1p;   cudaGetSymbolAddress((void**)&w1p,   g_w1h);
    __half* w3p;   cudaGetSymbolAddress((void**)&w3p,   g_w3h);
    __half* w2p;   cudaGetSymbolAddress((void**)&w2p,   g_w2h);

    cudaFuncSetAttribute(moe_gemm<0>, cudaFuncAttributeMaxDynamicSharedMemorySize, SMEM_BYTES);
    cudaFuncSetAttribute(moe_gemm<1>, cudaFuncAttributeMaxDynamicSharedMemorySize, SMEM_BYTES);
    cudaFuncSetAttribute(moe_gemm<2>, cudaFuncAttributeMaxDynamicSharedMemorySize, SMEM_BYTES);

    const size_t WSZ = (size_t)EE * II * HH;       // 132,710,400
    dim3 ggrid(HH / BN, 16, EE);   // (18, 16, 16) for BM=64

    // Order chosen so moe_gemm<0> is the 6th launch (ncu -s 5 -c 1 window).
    cvt16<<<(TT * HH) / 2048, 256>>>(x, x16p);     // 1
    cvt16<<<WSZ / 2048, 256>>>(w1, w1p);           // 2
    router_kernel<<<TT, 128>>>(x, rw, rb);         // 3
    group_kernel<<<1, 512>>>();                    // 4
    cvt16<<<WSZ / 2048, 256>>>(w3, w3p);           // 5
    moe_gemm<0><<<ggrid, 256, SMEM_BYTES>>>(w1p, b1);   // 6 <- profiled
    moe_gemm<1><<<ggrid, 256, SMEM_BYTES>>>(w3p, b3);   // 7
    act_kernel<<<(NROWS * II) / (256 * 4), 256>>>();    // 8
    cvt16<<<WSZ / 2048, 256>>>(w2, w2p);                // 9
    moe_gemm<2><<<ggrid, 256, SMEM_BYTES>>>(w2p, b2);   // 10
    combine_kernel<<<TT, 256>>>(y);                     // 11
}

// round 16
// speedup vs baseline: 3.0376x; 1.0768x over previous
#include <cuda_runtime.h>
#include <cuda_fp16.h>
#include <math.h>
#include <stdint.h>

#define TT 1024
#define HH 2880
#define II 2880
#define EE 16
#define KTOP 4
#define NROWS (TT * KTOP)
#define ALPHA 1.702f
#define LIMIT 7.0f

// fp16 GEMM tiling: BM=64, BN=160, BKH=64 halves; 2 CTAs/SM
#define BM 64
#define BN 160
#define BKH 64
#define NKT (HH / BKH)            // 45
#define A_ST (BM * 128)           // 8192 B per stage
#define B_ST (BN * 128)           // 20480 B per stage
#define STG (A_ST + B_ST)         // 28672
#define NST 4
#define SMEM_BYTES (NST * STG)    // 114688 (x2 CTAs = 229376 <= 228KB SM)

// fused converter: 72 CTAs x 256 thr x 8 elems x 900 iters = 132,710,400
#define CVT_CTAS 72
#define CVT_ITERS 900

// ---------------- scratch -----------------------------------------------
__device__ float  g_gate[(size_t)NROWS * II];
__device__ float  g_dn[(size_t)NROWS * HH];
__device__ __half g_h16[(size_t)NROWS * II];     // act output (GEMM3 A)
__device__ __half g_x16[(size_t)TT * HH];        // x in fp16
__device__ __half g_w1h[(size_t)EE * II * HH];
__device__ __half g_w3h[(size_t)EE * II * HH];
__device__ __half g_w2h[(size_t)EE * HH * II];
__device__ int    g_offs[EE + 1];
__device__ int    g_pos[NROWS];
__device__ int    g_rowtok[NROWS];
__device__ float  g_roww[NROWS];
__device__ int    g_tidx[NROWS];
__device__ float  g_tw[NROWS];

// ---------------- helpers -----------------------------------------------
__device__ __forceinline__ unsigned pack_h2(float lo, float hi) {
    __half2 h = __floats2half2_rn(lo, hi);
    return *reinterpret_cast<unsigned*>(&h);
}
__device__ __forceinline__ uint32_t smem_u32(const void* p) {
    uint32_t a;
    asm("{ .reg .u64 t; cvta.to.shared.u64 t, %1; cvt.u32.u64 %0, t; }" : "=r"(a) : "l"(p));
    return a;
}
__device__ __forceinline__ uint32_t SWZ(uint32_t off) {
    return off ^ ((off >> 3) & 0x70u);
}
#define CP_ASYNC16(dst, src)                                                \
    asm volatile("cp.async.cg.shared.global [%0], [%1], 16;" ::"r"(dst), "l"(src) : "memory")
#define CP_COMMIT() asm volatile("cp.async.commit_group;" ::: "memory")
#define CP_WAIT2()  asm volatile("cp.async.wait_group 2;" ::: "memory")

__device__ __forceinline__ void ldsm4(unsigned* r, uint32_t addr) {
    asm volatile("ldmatrix.sync.aligned.m8n8.x4.shared.b16 {%0,%1,%2,%3}, [%4];"
                 : "=r"(r[0]), "=r"(r[1]), "=r"(r[2]), "=r"(r[3]) : "r"(addr));
}
__device__ __forceinline__ void ldsm2(unsigned* r, uint32_t addr) {
    asm volatile("ldmatrix.sync.aligned.m8n8.x2.shared.b16 {%0,%1}, [%2];"
                 : "=r"(r[0]), "=r"(r[1]) : "r"(addr));
}
__device__ __forceinline__ void mma16(float* d, const unsigned* a, const unsigned* b) {
    asm volatile(
        "mma.sync.aligned.m16n8k16.row.col.f32.f16.f16.f32 "
        "{%0,%1,%2,%3}, {%4,%5,%6,%7}, {%8,%9}, {%0,%1,%2,%3};"
        : "+f"(d[0]), "+f"(d[1]), "+f"(d[2]), "+f"(d[3])
        : "r"(a[0]), "r"(a[1]), "r"(a[2]), "r"(a[3]), "r"(b[0]), "r"(b[1]));
}

// ---------------- fp32 -> fp16 streaming convert (standalone) ------------
__global__ void cvt16(const float* __restrict__ s, __half* __restrict__ d) {
    size_t i = ((size_t)blockIdx.x * 256 + threadIdx.x) * 8;
    float4 a = *(const float4*)(s + i);
    float4 b = *(const float4*)(s + i + 4);
    uint4 o;
    o.x = pack_h2(a.x, a.y);
    o.y = pack_h2(a.z, a.w);
    o.z = pack_h2(b.x, b.y);
    o.w = pack_h2(b.z, b.w);
    *(uint4*)((char*)d + i * 2) = o;
}

// ---------------- router ------------------------------------------------
__global__ void router_kernel(const float* __restrict__ x,
                              const float* __restrict__ rw,
                              const float* __restrict__ rb) {
    int t = blockIdx.x;
    int tid = threadIdx.x;
    float acc[EE];
#pragma unroll
    for (int e = 0; e < EE; e++) acc[e] = 0.f;
    const float* xr = x + (size_t)t * HH;
    for (int h = tid; h < HH; h += 128) {
        float xv = xr[h];
#pragma unroll
        for (int e = 0; e < EE; e++) acc[e] = fmaf(xv, rw[e * HH + h], acc[e]);
    }
#pragma unroll
    for (int e = 0; e < EE; e++) {
#pragma unroll
        for (int o = 16; o > 0; o >>= 1) acc[e] += __shfl_xor_sync(0xffffffffu, acc[e], o);
    }
    __shared__ float sl[4][EE];
    int w = tid >> 5;
    if ((tid & 31) == 0) {
#pragma unroll
        for (int e = 0; e < EE; e++) sl[w][e] = acc[e];
    }
    __syncthreads();
    if (tid == 0) {
        float lg[EE];
        float mx = -1e30f;
#pragma unroll
        for (int e = 0; e < EE; e++) {
            lg[e] = sl[0][e] + sl[1][e] + sl[2][e] + sl[3][e] + rb[e];
            mx = fmaxf(mx, lg[e]);
        }
        float p[EE];
#pragma unroll
        for (int e = 0; e < EE; e++) p[e] = __expf(lg[e] - mx);
        bool used[EE];
#pragma unroll
        for (int e = 0; e < EE; e++) used[e] = false;
        int sel[KTOP]; float pv[KTOP]; float psum = 0.f;
        for (int k = 0; k < KTOP; k++) {
            int best = 0; float bv = -1.f;
            for (int e = 0; e < EE; e++)
                if (!used[e] && p[e] > bv) { bv = p[e]; best = e; }
            used[best] = true; sel[k] = best; pv[k] = bv; psum += bv;
        }
        float inv = 1.f / psum;
        for (int k = 0; k < KTOP; k++) {
            g_tidx[t * 4 + k] = sel[k];
            g_tw[t * 4 + k]   = pv[k] * inv;
        }
    }
}

// ---------------- deterministic grouping: 16 blocks, 1 expert each -------
// Stable placement (original index order) — identical result to serial ver.
__global__ void group_kernel() {
    __shared__ int cnt[EE];
    __shared__ unsigned char eid[NROWS];
    __shared__ int chunkpre[128];
    const int b = blockIdx.x;          // expert handled by this block
    const int tid = threadIdx.x;       // 256 threads
    const int warp = tid >> 5, lane = tid & 31;
    if (tid < EE) cnt[tid] = 0;
    __syncthreads();
    for (int i = tid; i < NROWS; i += 256) {
        int ev = g_tidx[i];
        eid[i] = (unsigned char)ev;
        atomicAdd(&cnt[ev], 1);        // smem int add: order-independent
    }
    __syncthreads();
    int base = 0;
    for (int e2 = 0; e2 < b; e2++) base += cnt[e2];
    if (tid == 0) {
        g_offs[b] = base;
        if (b == EE - 1) g_offs[EE] = base + cnt[b];
    }
    // per-chunk (32 elems) match counts
    for (int ch = warp; ch < 128; ch += 8) {
        bool m = (eid[ch * 32 + lane] == (unsigned char)b);
        unsigned mask = __ballot_sync(0xffffffffu, m);
        if (lane == 0) chunkpre[ch] = __popc(mask);
    }
    __syncthreads();
    if (tid == 0) {
        int s = 0;
        for (int ch = 0; ch < 128; ch++) { int c = chunkpre[ch]; chunkpre[ch] = s; s += c; }
    }
    __syncthreads();
    const unsigned lt = (lane == 0) ? 0u : (0xffffffffu >> (32 - lane));
    for (int ch = warp; ch < 128; ch += 8) {
        int i = ch * 32 + lane;
        bool m = (eid[i] == (unsigned char)b);
        unsigned mask = __ballot_sync(0xffffffffu, m);
        if (m) {
            int pos = base + chunkpre[ch] + __popc(mask & lt);
            g_pos[i] = pos;
            g_rowtok[pos] = i >> 2;
            g_roww[pos] = g_tw[i];
        }
    }
}

// ---------------- grouped GEMM + fused weight convert + fused act --------
// z==0 slice: 72 CTAs convert cvt_src -> cvt_dst (next GEMM's weights).
// z>=1: expert e = z-1 GEMM.
// MODE 0: gate = gather(x16) @ w1h^T + b1       -> g_gate (fp32)
// MODE 1: up; epilogue applies clipped SwiGLU with g_gate -> g_h16 (fp16)
// MODE 2: dn = w * (h16 @ w2h^T + b2)           -> g_dn   (fp32)
template<int MODE>
__global__ __launch_bounds__(256, 2)
void moe_gemm(const __half* __restrict__ Wh, const float* __restrict__ Bias,
              const float* __restrict__ cvt_src, __half* __restrict__ cvt_dst) {
    if (blockIdx.z == 0) {
        if (MODE != 2) {
            int bi = blockIdx.y * gridDim.x + blockIdx.x;
            if (bi < CVT_CTAS) {
                const size_t stride = (size_t)CVT_CTAS * 256 * 8;
                size_t i = ((size_t)bi * 256 + threadIdx.x) * 8;
#pragma unroll 4
                for (int it = 0; it < CVT_ITERS; ++it, i += stride) {
                    float4 a = *(const float4*)(cvt_src + i);
                    float4 b4 = *(const float4*)(cvt_src + i + 4);
                    uint4 o;
                    o.x = pack_h2(a.x, a.y);
                    o.y = pack_h2(a.z, a.w);
                    o.z = pack_h2(b4.x, b4.y);
                    o.w = pack_h2(b4.z, b4.w);
                    *(uint4*)((char*)cvt_dst + i * 2) = o;
                }
            }
        }
        return;
    }
    const int e = blockIdx.z - 1;
    const int gbase = g_offs[e];
    const int Me = g_offs[e + 1] - gbase;
    const int m0 = blockIdx.y * BM;
    if (m0 >= Me) return;
    const int n0 = blockIdx.x * BN;

    extern __shared__ char smraw[];
    const uint32_t sb = smem_u32(smraw);
    const int tid = threadIdx.x;
    const int lane = tid & 31;
    const int warp = tid >> 5;
    const int wm = warp >> 2;                  // 0..1 (M 32 each)
    const int wn = warp & 3;                   // 0..3 (N 40 each)

    float acc[2][5][4];
#pragma unroll
    for (int i = 0; i < 2; i++)
#pragma unroll
        for (int j = 0; j < 5; j++)
#pragma unroll
            for (int q = 0; q < 4; q++) acc[i][j][q] = 0.f;

    // ---- A cp.async chunks: 512 total, 2 per thread ----
    const __half* gA[2]; uint32_t sA[2];
#pragma unroll
    for (int j = 0; j < 2; j++) {
        int c = tid + j * 256;
        int row = c >> 3, kc = c & 7;
        int r = m0 + row;
        if (r >= Me) r = 0;                    // clamp: garbage-safe (row unstored)
        const __half* rowp;
        if (MODE == 2) rowp = g_h16 + (size_t)(gbase + r) * II;
        else           rowp = g_x16 + (size_t)g_rowtok[gbase + r] * HH;
        gA[j] = rowp + kc * 8;
        sA[j] = SWZ((uint32_t)(row * 128 + kc * 16));
    }
    // ---- B cp.async chunks: 1280 total, 5 per thread ----
    const __half* gB[5]; uint32_t sB[5];
#pragma unroll
    for (int j = 0; j < 5; j++) {
        int c = tid + j * 256;
        int row = c >> 3, kc = c & 7;
        gB[j] = Wh + (size_t)e * HH * II + (size_t)(n0 + row) * HH + kc * 8;
        sB[j] = A_ST + SWZ((uint32_t)(row * 128 + kc * 16));
    }

#define ISSUE(st)                                                            \
    do {                                                                     \
        uint32_t _b = sb + ((st) & 3) * STG;                                 \
        int _k = (st) * BKH;                                                 \
        CP_ASYNC16(_b + sA[0], gA[0] + _k);                                  \
        CP_ASYNC16(_b + sA[1], gA[1] + _k);                                  \
        CP_ASYNC16(_b + sB[0], gB[0] + _k);                                  \
        CP_ASYNC16(_b + sB[1], gB[1] + _k);                                  \
        CP_ASYNC16(_b + sB[2], gB[2] + _k);                                  \
        CP_ASYNC16(_b + sB[3], gB[3] + _k);                                  \
        CP_ASYNC16(_b + sB[4], gB[4] + _k);                                  \
    } while (0)

    // ---- ldsm raw offsets + per-lane swizzle masks ----
    const uint32_t axorm = (uint32_t)((lane & 7) << 4);
    const int lane15 = lane & 15;
    const uint32_t b2xor = (uint32_t)((lane15 & 7) << 4);
    uint32_t araw[2];
#pragma unroll
    for (int mt = 0; mt < 2; mt++) {
        int R = wm * 32 + mt * 16 + (lane & 7) + ((lane >> 3) & 1) * 8;
        araw[mt] = (uint32_t)(R * 128 + ((lane >> 4) & 1) * 16);
    }
    const uint32_t braw0 = (uint32_t)(A_ST + (wn * 40 + (lane & 7) + ((lane >> 4) & 1) * 8) * 128 +
                                      ((lane >> 3) & 1) * 16);
    const uint32_t braw1 = braw0 + 16 * 128;
    const uint32_t braw2 = (uint32_t)(A_ST + (wn * 40 + 32 + (lane15 & 7)) * 128 +
                                      ((lane15 >> 3) & 1) * 16);

    unsigned af[2][4], bt0[2][4], bt1[2][4], bt2[2][2];

#define LOADA(bbase, ks)                                                     \
    do {                                                                     \
        uint32_t _o = (uint32_t)((ks) * 32);                                 \
        ldsm4(af[0], (bbase) + ((araw[0] + _o) ^ axorm));                    \
        ldsm4(af[1], (bbase) + ((araw[1] + _o) ^ axorm));                    \
    } while (0)
#define LOADB(buf, bbase, ks)                                                \
    do {                                                                     \
        uint32_t _o = (uint32_t)((ks) * 32);                                 \
        ldsm4(bt0[buf], (bbase) + ((braw0 + _o) ^ axorm));                   \
        ldsm4(bt1[buf], (bbase) + ((braw1 + _o) ^ axorm));                   \
        ldsm2(bt2[buf], (bbase) + ((braw2 + _o) ^ b2xor));                   \
    } while (0)
#define MMAS(buf)                                                            \
    do {                                                                     \
        _Pragma("unroll")                                                    \
        for (int mt = 0; mt < 2; mt++) {                                     \
            mma16(acc[mt][0], af[mt], &bt0[buf][0]);                         \
            mma16(acc[mt][1], af[mt], &bt0[buf][2]);                         \
            mma16(acc[mt][2], af[mt], &bt1[buf][0]);                         \
            mma16(acc[mt][3], af[mt], &bt1[buf][2]);                         \
            mma16(acc[mt][4], af[mt], bt2[buf]);                             \
        }                                                                    \
    } while (0)

    // ---- prologue: stages 0..2 in flight ----
    ISSUE(0); CP_COMMIT();
    ISSUE(1); CP_COMMIT();
    ISSUE(2); CP_COMMIT();

#pragma unroll 1
    for (int kt = 0; kt < NKT; ++kt) {
        CP_WAIT2();            // stage kt (own chunks) complete
        __syncthreads();       // visible to all; slot (kt-1)&3 free
        if (kt + 3 < NKT) ISSUE(kt + 3);
        CP_COMMIT();

        uint32_t base = sb + (kt & 3) * STG;
        LOADB(0, base, 0);
        // ks0
        LOADA(base, 0); LOADB(1, base, 1); MMAS(0);
        // ks1
        LOADA(base, 1); LOADB(0, base, 2); MMAS(1);
        // ks2
        LOADA(base, 2); LOADB(1, base, 3); MMAS(0);
        // ks3
        LOADA(base, 3); MMAS(1);
    }

    // ---- epilogue ----
#pragma unroll
    for (int mt = 0; mt < 2; mt++) {
        int rloc0 = wm * 32 + mt * 16 + (lane >> 2);
#pragma unroll
        for (int half = 0; half < 2; half++) {
            int r = m0 + rloc0 + half * 8;
            if (r >= Me) continue;
            size_t orow = (size_t)(gbase + r) * (size_t)((MODE == 2) ? HH : II);
            if (MODE == 1) {
                // fused clipped SwiGLU: up in regs, gate from g_gate, out fp16
                const float* grow = g_gate + orow;
#pragma unroll
                for (int nt = 0; nt < 5; nt++) {
                    int col = n0 + wn * 40 + nt * 8 + (lane & 3) * 2;
                    float u0 = acc[mt][nt][half * 2 + 0] + Bias[e * HH + col];
                    float u1 = acc[mt][nt][half * 2 + 1] + Bias[e * HH + col + 1];
                    float a0 = grow[col], a1 = grow[col + 1];
                    float gg0 = fminf(a0, LIMIT);
                    float gg1 = fminf(a1, LIMIT);
                    float uu0 = fminf(fmaxf(u0, -LIMIT), LIMIT);
                    float uu1 = fminf(fmaxf(u1, -LIMIT), LIMIT);
                    float s0 = 1.f / (1.f + __expf(-ALPHA * gg0));
                    float s1 = 1.f / (1.f + __expf(-ALPHA * gg1));
                    float h0 = (uu0 + 1.f) * (gg0 * s0);
                    float h1 = (uu1 + 1.f) * (gg1 * s1);
                    *(unsigned*)((char*)g_h16 + (orow + col) * 2) = pack_h2(h0, h1);
                }
            } else {
                float* Out = (MODE == 0) ? g_gate : g_dn;
                float wgt = (MODE == 2) ? g_roww[gbase + r] : 1.f;
#pragma unroll
                for (int nt = 0; nt < 5; nt++) {
                    int col = n0 + wn * 40 + nt * 8 + (lane & 3) * 2;
                    float v0 = acc[mt][nt][half * 2 + 0] + Bias[e * HH + col];
                    float v1 = acc[mt][nt][half * 2 + 1] + Bias[e * HH + col + 1];
                    if (MODE == 2) { v0 *= wgt; v1 *= wgt; }
                    Out[orow + col]     = v0;
                    Out[orow + col + 1] = v1;
                }
            }
        }
    }
#undef ISSUE
#undef LOADA
#undef LOADB
#undef MMAS
}

// ---------------- per-token fixed-order combine -------------------------
__global__ void combine_kernel(float* __restrict__ y) {
    int t = blockIdx.x;
    const float* r0 = g_dn + (size_t)g_pos[t * 4 + 0] * HH;
    const float* r1 = g_dn + (size_t)g_pos[t * 4 + 1] * HH;
    const float* r2 = g_dn + (size_t)g_pos[t * 4 + 2] * HH;
    const float* r3 = g_dn + (size_t)g_pos[t * 4 + 3] * HH;
    float* yo = y + (size_t)t * HH;
    for (int c = threadIdx.x * 4; c < HH; c += 256 * 4) {
        float4 a = *(const float4*)(r0 + c);
        float4 b = *(const float4*)(r1 + c);
        float4 d = *(const float4*)(r2 + c);
        float4 f = *(const float4*)(r3 + c);
        *(float4*)(yo + c) = make_float4(a.x + b.x + d.x + f.x, a.y + b.y + d.y + f.y,
                                         a.z + b.z + d.z + f.z, a.w + b.w + d.w + f.w);
    }
}

// ---------------- launch ------------------------------------------------
extern "C" void kernel_launch(void* const* d_in, const int* in_sizes, int n_in,
                              void* d_out, int out_size) {
    const float* x  = (const float*)d_in[0];
    const float* rw = (const float*)d_in[1];
    const float* rb = (const float*)d_in[2];
    const float* w1 = (const float*)d_in[3];
    const float* b1 = (const float*)d_in[4];
    const float* w3 = (const float*)d_in[5];
    const float* b3 = (const float*)d_in[6];
    const float* w2 = (const float*)d_in[7];
    const float* b2 = (const float*)d_in[8];
    float* y = (float*)d_out;

    __half* x16p;  cudaGetSymbolAddress((void**)&x16p,  g_x16);
    __half* w1p;   cudaGetSymbolAddress((void**)&w1p,   g_w1h);
    __half* w3p;   cudaGetSymbolAddress((void**)&w3p,   g_w3h);
    __half* w2p;   cudaGetSymbolAddress((void**)&w2p,   g_w2h);

    cudaFuncSetAttribute(moe_gemm<0>, cudaFuncAttributeMaxDynamicSharedMemorySize, SMEM_BYTES);
    cudaFuncSetAttribute(moe_gemm<1>, cudaFuncAttributeMaxDynamicSharedMemorySize, SMEM_BYTES);
    cudaFuncSetAttribute(moe_gemm<2>, cudaFuncAttributeMaxDynamicSharedMemorySize, SMEM_BYTES);

    const size_t WSZ = (size_t)EE * II * HH;       // 132,710,400
    dim3 ggrid(HH / BN, 16, EE + 1);   // (18, 16, 17); z=0 = converter slice

    cvt16<<<(TT * HH) / 2048, 256>>>(x, x16p);          // 1
    cvt16<<<WSZ / 2048, 256>>>(w1, w1p);                // 2
    router_kernel<<<TT, 128>>>(x, rw, rb);              // 3
    group_kernel<<<EE, 256>>>();                        // 4
    moe_gemm<0><<<ggrid, 256, SMEM_BYTES>>>(w1p, b1, w3, w3p);   // 5 (+cvt w3)
    moe_gemm<1><<<ggrid, 256, SMEM_BYTES>>>(w3p, b3, w2, w2p);   // 6 (+cvt w2, act)
    moe_gemm<2><<<ggrid, 256, SMEM_BYTES>>>(w2p, b2, nullptr, nullptr);  // 7
    combine_kernel<<<TT, 256>>>(y);                     // 8
}